// round 7
// baseline (speedup 1.0000x reference)
#include <cuda_runtime.h>
#include <cuda_bf16.h>
#include <cstdint>

#define BB 16
#define TT 512
#define VV 64
#define HH 64
#define BT (BB*TT)
#define VH (VV*HH)
#define TC 256

// ---------------- scratch ----------------------------------------------------
__device__ __nv_bfloat16 g_adjH[BB*4096], g_adjL[BB*4096]; // swizzled tiles [b][v][w]
__device__ __nv_bfloat16 g_w1H[1024],  g_w1L[1024];        // swizzled [c=16][h=64]
__device__ __nv_bfloat16 g_w2H[4096],  g_w2L[4096];        // swizzled [h][o]
__device__ float g_z1[(size_t)BT*VH];                      // fp32 [bt][v][h]
__device__ __nv_bfloat16 g_z2b[(size_t)BT*VH];             // bf16 [bt][v][o]
__device__ float g_psum1[HH*BT], g_psq1[HH*BT];
__device__ float g_psum2[HH*BT], g_psq2[HH*BT];
__device__ float g_a1[HH], g_c1[HH], g_a2[HH], g_c2[HH];
__device__ float g_S1p[(size_t)BB*128*VH];                 // per-CTA x1 sums (33.5MB)
__device__ float g_E0x1[BB*VH], g_E1x1[BB*VH];
__device__ float g_S[BB*VH], g_E0[BB*VH], g_E1[BB*VH];
__device__ float g_y[BB*TC];

extern __shared__ unsigned char s_dyn[];

// ---------------- helpers -----------------------------------------------------
__device__ __forceinline__ uint32_t toff(int r, int cB) {
    return (uint32_t)(r*128 + (cB ^ ((r & 7) << 4)));
}
__device__ __forceinline__ int zoff(int r, int c) {
    return r*64 + ((((c >> 2) ^ r) & 15) << 2) + (c & 3);
}
__device__ __forceinline__ void ldsm4(uint32_t* r, unsigned char* p) {
    uint32_t a; asm("{ .reg .u64 t; cvta.to.shared.u64 t, %1; cvt.u32.u64 %0, t; }" : "=r"(a) : "l"(p));
    asm volatile("ldmatrix.sync.aligned.m8n8.x4.shared.b16 {%0,%1,%2,%3}, [%4];"
        : "=r"(r[0]), "=r"(r[1]), "=r"(r[2]), "=r"(r[3]) : "r"(a));
}
__device__ __forceinline__ void ldsm2t(uint32_t& r0, uint32_t& r1, unsigned char* p) {
    uint32_t a; asm("{ .reg .u64 t; cvta.to.shared.u64 t, %1; cvt.u32.u64 %0, t; }" : "=r"(a) : "l"(p));
    asm volatile("ldmatrix.sync.aligned.m8n8.x2.trans.shared.b16 {%0,%1}, [%2];"
        : "=r"(r0), "=r"(r1) : "r"(a));
}
__device__ __forceinline__ void mmabf(float* c, const uint32_t* a, uint32_t b0, uint32_t b1) {
    asm volatile("mma.sync.aligned.m16n8k16.row.col.f32.bf16.bf16.f32 "
        "{%0,%1,%2,%3},{%4,%5,%6,%7},{%8,%9},{%0,%1,%2,%3};"
        : "+f"(c[0]), "+f"(c[1]), "+f"(c[2]), "+f"(c[3])
        : "r"(a[0]), "r"(a[1]), "r"(a[2]), "r"(a[3]), "r"(b0), "r"(b1));
}
__device__ __forceinline__ void split2(float f0, float f1, uint32_t& hi, uint32_t& lo) {
    asm("cvt.rn.bf16x2.f32 %0, %1, %2;" : "=r"(hi) : "f"(f1), "f"(f0));
    float h0 = __uint_as_float(hi << 16);
    float h1 = __uint_as_float(hi & 0xffff0000u);
    asm("cvt.rn.bf16x2.f32 %0, %1, %2;" : "=r"(lo) : "f"(f1 - h1), "f"(f0 - h0));
}
__device__ __forceinline__ uint32_t packbf(float f0, float f1) {
    uint32_t r;
    asm("cvt.rn.bf16x2.f32 %0, %1, %2;" : "=r"(r) : "f"(f1), "f"(f0));
    return r;
}
__device__ __forceinline__ void lda(uint32_t* a, unsigned char* base, int mt, int kt, int lane) {
    int row = mt*16 + (lane & 7) + (lane & 8);
    int cB  = kt*32 + ((lane >> 4) << 4);
    ldsm4(a, base + toff(row, cB));
}
__device__ __forceinline__ void ldb(uint32_t& b0, uint32_t& b1, unsigned char* base, int kt, int nt, int lane) {
    int row = kt*16 + (lane & 15);
    ldsm2t(b0, b1, base + toff(row, nt*16));
}

// ---------------- K0: prep ----------------------------------------------------
__global__ void k_prep(const float* __restrict__ adj, const float* __restrict__ w1,
                       const float* __restrict__ w2) {
    int b = blockIdx.x, tid = threadIdx.x;
    __shared__ float dis[64];
    const float* A = adj + b*4096;
    if (tid < 64) {
        float s = 0.f;
        #pragma unroll 8
        for (int w = 0; w < 64; w++) s += A[tid*64 + w];
        dis[tid] = rsqrtf(s + 1e-6f);
    }
    __syncthreads();
    for (int idx = tid; idx < 4096; idx += 256) {
        int v = idx >> 6, w = idx & 63;
        float a = dis[v] * A[idx] * dis[w];
        __nv_bfloat16 hb = __float2bfloat16(a);
        __nv_bfloat16 lb = __float2bfloat16(a - __bfloat162float(hb));
        uint32_t e = toff(v, w*2) >> 1;
        g_adjH[b*4096 + e] = hb; g_adjL[b*4096 + e] = lb;
    }
    if (b == 0) {
        for (int idx = tid; idx < 1024; idx += 256) {
            int c = idx >> 6, h = idx & 63;
            float val = w1[c*64 + h];
            __nv_bfloat16 hb = __float2bfloat16(val);
            __nv_bfloat16 lb = __float2bfloat16(val - __bfloat162float(hb));
            uint32_t e = toff(c, h*2) >> 1;
            g_w1H[e] = hb; g_w1L[e] = lb;
        }
        for (int idx = tid; idx < 4096; idx += 256) {
            int h = idx >> 6, o = idx & 63;
            float val = w2[h*64 + o];
            __nv_bfloat16 hb = __float2bfloat16(val);
            __nv_bfloat16 lb = __float2bfloat16(val - __bfloat162float(hb));
            uint32_t e = toff(h, o*2) >> 1;
            g_w2H[e] = hb; g_w2L[e] = lb;
        }
    }
}

// ---------------- epilogues ----------------------------------------------------
__device__ __forceinline__ void stage_stats(float acc[4][8][4], float* zs, int lane,
                                            float* psum, float* psq, int bt) {
    #pragma unroll
    for (int mt = 0; mt < 4; mt++)
        #pragma unroll
        for (int nt = 0; nt < 8; nt++) {
            int r = mt*16 + (lane >> 2), c = nt*8 + (lane & 3)*2;
            *(float2*)&zs[zoff(r, c)]   = make_float2(acc[mt][nt][0], acc[mt][nt][1]);
            *(float2*)&zs[zoff(r+8, c)] = make_float2(acc[mt][nt][2], acc[mt][nt][3]);
        }
    __syncwarp();
    float s0 = 0.f, q0 = 0.f, s1 = 0.f, q1 = 0.f;
    #pragma unroll 8
    for (int r = 0; r < 64; r++) {
        float v0 = zs[zoff(r, lane)];
        float v1 = zs[zoff(r, lane + 32)];
        s0 += v0; q0 += v0*v0; s1 += v1; q1 += v1*v1;
    }
    psum[lane*BT + bt] = s0; psum[(lane+32)*BT + bt] = s1;
    psq[lane*BT + bt]  = q0; psq[(lane+32)*BT + bt]  = q1;
}
__device__ __forceinline__ void epilogue_f32(float acc[4][8][4], float* zs, int lane,
                                             float* zout, float* psum, float* psq, int bt) {
    stage_stats(acc, zs, lane, psum, psq, bt);
    #pragma unroll
    for (int it = 0; it < 32; it++) {
        int idx = it*32 + lane;
        int r = idx >> 4, cq = (idx & 15) << 2;
        *(float4*)&zout[r*64 + cq] = *(float4*)&zs[zoff(r, cq)];
    }
}
__device__ __forceinline__ void epilogue_bf(float acc[4][8][4], float* zs, int lane,
                                            __nv_bfloat16* zout, float* psum, float* psq, int bt) {
    stage_stats(acc, zs, lane, psum, psq, bt);
    #pragma unroll
    for (int it = 0; it < 32; it++) {
        int idx = it*32 + lane;
        int r = idx >> 4, cq = (idx & 15) << 2;
        float4 v = *(float4*)&zs[zoff(r, cq)];
        uint32_t p0 = packbf(v.x, v.y), p1 = packbf(v.z, v.w);
        *(uint2*)((unsigned char*)zout + (size_t)(r*64 + cq)*2) = make_uint2(p0, p1);
    }
}

// ---------------- K1: layer1 HMMA ----------------------------------------------
#define L1_WREG 20480
#define L1_SM   (20480 + 4*16384)
__global__ void __launch_bounds__(128, 2) k_l1(const float* __restrict__ x) {
    int blk = blockIdx.x, b = blk >> 7, chunk = blk & 127;
    int tid = threadIdx.x, lane = tid & 31, wq = tid >> 5;
    unsigned char* sm = s_dyn;
    {
        const uint4* s1 = (const uint4*)(g_adjH + b*4096);
        const uint4* s2 = (const uint4*)(g_adjL + b*4096);
        uint4* d1 = (uint4*)sm; uint4* d2 = (uint4*)(sm + 8192);
        for (int i = tid; i < 512; i += 128) { d1[i] = s1[i]; d2[i] = s2[i]; }
        const uint4* s3 = (const uint4*)g_w1H; const uint4* s4 = (const uint4*)g_w1L;
        uint4* d3 = (uint4*)(sm + 16384); uint4* d4 = (uint4*)(sm + 18432);
        if (tid < 128) { d3[tid] = s3[tid]; d4[tid] = s4[tid]; }
    }
    __syncthreads();

    int t = chunk*4 + wq;
    int bt = b*TT + t;
    unsigned char* XH = sm + L1_WREG + wq*16384;
    unsigned char* XL = XH + 8192;
    unsigned char* AH = sm; unsigned char* AL = sm + 8192;
    unsigned char* WH = sm + 16384; unsigned char* WL = sm + 18432;

    const float* xg = x + (size_t)bt*1024;
    #pragma unroll
    for (int it = 0; it < 8; it++) {
        int idx = it*32 + lane;
        int r = idx >> 2, cq = (idx & 3) << 2;
        float4 u = *(const float4*)&xg[r*16 + cq];
        uint32_t h01, l01, h23, l23;
        split2(u.x, u.y, h01, l01); split2(u.z, u.w, h23, l23);
        uint32_t off = toff(r, cq*2);
        *(uint2*)(XH + off) = make_uint2(h01, h23);
        *(uint2*)(XL + off) = make_uint2(l01, l23);
    }
    __syncwarp();

    // GEMM1': tmp[v][c] = sum_w A[v][w] X[w][c]
    float acc1[4][2][4];
    #pragma unroll
    for (int m = 0; m < 4; m++)
        #pragma unroll
        for (int n = 0; n < 2; n++) { acc1[m][n][0]=0; acc1[m][n][1]=0; acc1[m][n][2]=0; acc1[m][n][3]=0; }
    #pragma unroll
    for (int kt = 0; kt < 4; kt++) {
        uint32_t aH[4][4], aL[4][4];
        #pragma unroll
        for (int mt = 0; mt < 4; mt++) { lda(aH[mt], AH, mt, kt, lane); lda(aL[mt], AL, mt, kt, lane); }
        #pragma unroll
        for (int nt = 0; nt < 2; nt++) {
            uint32_t bh0, bh1, bl0, bl1;
            ldb(bh0, bh1, XH, kt, nt, lane);
            ldb(bl0, bl1, XL, kt, nt, lane);
            #pragma unroll
            for (int mt = 0; mt < 4; mt++) {
                mmabf(acc1[mt][nt], aH[mt], bh0, bh1);
                mmabf(acc1[mt][nt], aL[mt], bh0, bh1);
                mmabf(acc1[mt][nt], aH[mt], bl0, bl1);
            }
        }
    }
    __syncwarp();
    #pragma unroll
    for (int mt = 0; mt < 4; mt++)
        #pragma unroll
        for (int nt = 0; nt < 2; nt++) {
            int r = mt*16 + (lane >> 2), cB = (nt*8 + (lane & 3)*2)*2;
            uint32_t h, l;
            split2(acc1[mt][nt][0], acc1[mt][nt][1], h, l);
            *(uint32_t*)(XH + toff(r, cB)) = h; *(uint32_t*)(XL + toff(r, cB)) = l;
            split2(acc1[mt][nt][2], acc1[mt][nt][3], h, l);
            *(uint32_t*)(XH + toff(r+8, cB)) = h; *(uint32_t*)(XL + toff(r+8, cB)) = l;
        }
    __syncwarp();

    // GEMM2': z1[v][h] = sum_c tmp[v][c] W1[c][h]
    float acc2[4][8][4];
    #pragma unroll
    for (int m = 0; m < 4; m++)
        #pragma unroll
        for (int n = 0; n < 8; n++) { acc2[m][n][0]=0; acc2[m][n][1]=0; acc2[m][n][2]=0; acc2[m][n][3]=0; }
    {
        uint32_t aH[4][4], aL[4][4];
        #pragma unroll
        for (int mt = 0; mt < 4; mt++) { lda(aH[mt], XH, mt, 0, lane); lda(aL[mt], XL, mt, 0, lane); }
        #pragma unroll
        for (int nt = 0; nt < 8; nt++) {
            uint32_t bh0, bh1, bl0, bl1;
            ldb(bh0, bh1, WH, 0, nt, lane);
            ldb(bl0, bl1, WL, 0, nt, lane);
            #pragma unroll
            for (int mt = 0; mt < 4; mt++) {
                mmabf(acc2[mt][nt], aH[mt], bh0, bh1);
                mmabf(acc2[mt][nt], aL[mt], bh0, bh1);
                mmabf(acc2[mt][nt], aH[mt], bl0, bl1);
            }
        }
    }
    __syncwarp();
    epilogue_f32(acc2, (float*)XH, lane, g_z1 + (size_t)bt*4096, g_psum1, g_psq1, bt);
}

// ---------------- K2: finalize BN affine ---------------------------------------
__global__ void k_stats(int layer, const float* __restrict__ g, const float* __restrict__ be) {
    int h = blockIdx.x, tid = threadIdx.x;
    const float* ps = layer ? g_psum2 : g_psum1;
    const float* pq = layer ? g_psq2  : g_psq1;
    __shared__ float ss[256], sq[256];
    float s = 0.f, q = 0.f;
    for (int i = tid; i < BT; i += 256) { s += ps[h*BT + i]; q += pq[h*BT + i]; }
    ss[tid] = s; sq[tid] = q;
    __syncthreads();
    for (int st = 128; st > 0; st >>= 1) {
        if (tid < st) { ss[tid] += ss[tid+st]; sq[tid] += sq[tid+st]; }
        __syncthreads();
    }
    if (tid == 0) {
        const float N = (float)(BT*VV);
        float mean = ss[0] / N;
        float var  = sq[0] / N - mean*mean;
        float av = g[h] * rsqrtf(var + 1e-5f);
        if (layer) { g_a2[h] = av; g_c2[h] = be[h] - mean*av; }
        else       { g_a1[h] = av; g_c1[h] = be[h] - mean*av; }
    }
}

// ---------------- K3: layer2 HMMA ----------------------------------------------
#define L2_WREG 33280
#define L2_SM   (33280 + 4*16384)
__global__ void __launch_bounds__(128, 2) k_l2() {
    int blk = blockIdx.x, b = blk >> 7, chunk = blk & 127;
    int tid = threadIdx.x, lane = tid & 31, wq = tid >> 5;
    unsigned char* sm = s_dyn;
    float* a1s = (float*)(sm + 32768);
    float* c1s = a1s + 64;
    {
        const uint4* s1 = (const uint4*)(g_adjH + b*4096);
        const uint4* s2 = (const uint4*)(g_adjL + b*4096);
        uint4* d1 = (uint4*)sm; uint4* d2 = (uint4*)(sm + 8192);
        for (int i = tid; i < 512; i += 128) { d1[i] = s1[i]; d2[i] = s2[i]; }
        const uint4* s3 = (const uint4*)g_w2H; const uint4* s4 = (const uint4*)g_w2L;
        uint4* d3 = (uint4*)(sm + 16384); uint4* d4 = (uint4*)(sm + 24576);
        for (int i = tid; i < 512; i += 128) { d3[i] = s3[i]; d4[i] = s4[i]; }
        if (tid < 64) { a1s[tid] = g_a1[tid]; c1s[tid] = g_c1[tid]; }
    }
    __syncthreads();

    int t = chunk*4 + wq;
    int bt = b*TT + t;
    bool isE0 = (t == 0), isE1 = (t == TT-1);
    unsigned char* XH = sm + L2_WREG + wq*16384;
    unsigned char* XL = XH + 8192;
    unsigned char* AH = sm; unsigned char* AL = sm + 8192;
    unsigned char* WH = sm + 16384; unsigned char* WL = sm + 24576;

    // build x1 tile [w=64][h=64] = relu(a1*z1+c1), bf16 hi/lo
    const float* zt = g_z1 + (size_t)bt*4096;
    #pragma unroll
    for (int it = 0; it < 32; it++) {
        int idx = it*32 + lane;
        int r = idx >> 4, cq = (idx & 15) << 2;
        float4 u = *(const float4*)&zt[r*64 + cq];
        float4 av = *(float4*)&a1s[cq];
        float4 cv = *(float4*)&c1s[cq];
        float e0 = fmaxf(fmaf(u.x, av.x, cv.x), 0.f);
        float e1 = fmaxf(fmaf(u.y, av.y, cv.y), 0.f);
        float e2 = fmaxf(fmaf(u.z, av.z, cv.z), 0.f);
        float e3 = fmaxf(fmaf(u.w, av.w, cv.w), 0.f);
        uint32_t h01, l01, h23, l23;
        split2(e0, e1, h01, l01); split2(e2, e3, h23, l23);
        uint32_t off = toff(r, cq*2);
        *(uint2*)(XH + off) = make_uint2(h01, h23);
        *(uint2*)(XL + off) = make_uint2(l01, l23);
        if (isE0) *(float4*)&g_E0x1[b*4096 + r*64 + cq] = make_float4(e0,e1,e2,e3);
        if (isE1) *(float4*)&g_E1x1[b*4096 + r*64 + cq] = make_float4(e0,e1,e2,e3);
    }

    // ---- cross-warp S1 partial: sum 4 warps' x1 tiles -> g_S1p[blk] ----
    __syncthreads();
    {
        int r = tid >> 1, ch = (tid & 1) << 5;
        float s[32];
        #pragma unroll
        for (int j = 0; j < 32; j++) s[j] = 0.f;
        #pragma unroll
        for (int w = 0; w < 4; w++) {
            unsigned char* WXH = sm + L2_WREG + w*16384;
            unsigned char* WXL = WXH + 8192;
            #pragma unroll
            for (int j = 0; j < 4; j++) {
                uint32_t off = toff(r, (ch + j*8)*2);
                uint4 uh = *(uint4*)(WXH + off);
                uint4 ul = *(uint4*)(WXL + off);
                uint32_t uu[8] = {uh.x,ul.x,uh.y,ul.y,uh.z,ul.z,uh.w,ul.w};
                #pragma unroll
                for (int q = 0; q < 4; q++) {
                    s[j*8+q*2]   += __uint_as_float(uu[2*q] << 16) + __uint_as_float(uu[2*q+1] << 16);
                    s[j*8+q*2+1] += __uint_as_float(uu[2*q] & 0xffff0000u) + __uint_as_float(uu[2*q+1] & 0xffff0000u);
                }
            }
        }
        float* dst = g_S1p + (size_t)blk*4096 + r*64 + ch;
        #pragma unroll
        for (int j = 0; j < 8; j++)
            *(float4*)&dst[j*4] = make_float4(s[4*j], s[4*j+1], s[4*j+2], s[4*j+3]);
    }
    __syncthreads();

    float acc[4][8][4];
    #pragma unroll
    for (int m = 0; m < 4; m++)
        #pragma unroll
        for (int n = 0; n < 8; n++) { acc[m][n][0]=0; acc[m][n][1]=0; acc[m][n][2]=0; acc[m][n][3]=0; }

    // GEMM1: tmp[v][h] = sum_w A[v][w] x1[w][h]
    #pragma unroll
    for (int kt = 0; kt < 4; kt++) {
        uint32_t aH[4][4], aL[4][4];
        #pragma unroll
        for (int mt = 0; mt < 4; mt++) { lda(aH[mt], AH, mt, kt, lane); lda(aL[mt], AL, mt, kt, lane); }
        #pragma unroll
        for (int nt = 0; nt < 8; nt++) {
            uint32_t bh0, bh1, bl0, bl1;
            ldb(bh0, bh1, XH, kt, nt, lane);
            ldb(bl0, bl1, XL, kt, nt, lane);
            #pragma unroll
            for (int mt = 0; mt < 4; mt++) {
                mmabf(acc[mt][nt], aH[mt], bh0, bh1);
                mmabf(acc[mt][nt], aL[mt], bh0, bh1);
                mmabf(acc[mt][nt], aH[mt], bl0, bl1);
            }
        }
    }
    __syncwarp();
    #pragma unroll
    for (int mt = 0; mt < 4; mt++)
        #pragma unroll
        for (int nt = 0; nt < 8; nt++) {
            int r = mt*16 + (lane >> 2), cB = (nt*8 + (lane & 3)*2)*2;
            uint32_t h, l;
            split2(acc[mt][nt][0], acc[mt][nt][1], h, l);
            *(uint32_t*)(XH + toff(r, cB)) = h; *(uint32_t*)(XL + toff(r, cB)) = l;
            split2(acc[mt][nt][2], acc[mt][nt][3], h, l);
            *(uint32_t*)(XH + toff(r+8, cB)) = h; *(uint32_t*)(XL + toff(r+8, cB)) = l;
        }
    __syncwarp();

    // GEMM2: z2[v][o] = sum_h tmp[v][h] W2[h][o]
    #pragma unroll
    for (int m = 0; m < 4; m++)
        #pragma unroll
        for (int n = 0; n < 8; n++) { acc[m][n][0]=0; acc[m][n][1]=0; acc[m][n][2]=0; acc[m][n][3]=0; }
    #pragma unroll
    for (int kt = 0; kt < 4; kt++) {
        uint32_t aH[4][4], aL[4][4];
        #pragma unroll
        for (int mt = 0; mt < 4; mt++) { lda(aH[mt], XH, mt, kt, lane); lda(aL[mt], XL, mt, kt, lane); }
        #pragma unroll
        for (int nt = 0; nt < 8; nt++) {
            uint32_t bh0, bh1, bl0, bl1;
            ldb(bh0, bh1, WH, kt, nt, lane);
            ldb(bl0, bl1, WL, kt, nt, lane);
            #pragma unroll
            for (int mt = 0; mt < 4; mt++) {
                mmabf(acc[mt][nt], aH[mt], bh0, bh1);
                mmabf(acc[mt][nt], aL[mt], bh0, bh1);
                mmabf(acc[mt][nt], aH[mt], bl0, bl1);
            }
        }
    }
    __syncwarp();
    epilogue_bf(acc, (float*)XH, lane, g_z2b + (size_t)bt*4096, g_psum2, g_psq2, bt);
}

// ---------------- K4: S = S1p + sum_t relu(BN(z2)); edges ----------------------
__global__ void __launch_bounds__(256) k_sumfinal() {
    int bv = blockIdx.x, b = bv >> 6, v = bv & 63;
    int tid = threadIdx.x, h2 = tid & 31, ph = tid >> 5;   // 8 phases
    int h0 = h2*2;
    float a20 = g_a2[h0], c20 = g_c2[h0], a21 = g_a2[h0+1], c21 = g_c2[h0+1];
    const uint32_t* zp = (const uint32_t*)g_z2b;
    size_t base = (size_t)b*TT*2048 + v*32 + h2;
    float s0 = 0.f, s1 = 0.f, e00 = 0.f, e01 = 0.f, e10 = 0.f, e11 = 0.f;
    #pragma unroll 4
    for (int t = ph; t < TT; t += 8) {
        uint32_t u = zp[base + (size_t)t*2048];
        float z0 = __uint_as_float(u << 16);
        float z1 = __uint_as_float(u & 0xffff0000u);
        float x0 = fmaxf(fmaf(z0, a20, c20), 0.f);
        float x1 = fmaxf(fmaf(z1, a21, c21), 0.f);
        s0 += x0; s1 += x1;
        if (t == 0)    { e00 = x0; e01 = x1; }
        if (t == TT-1) { e10 = x0; e11 = x1; }
    }
    #pragma unroll 4
    for (int c = ph; c < 128; c += 8) {
        float2 w = *(const float2*)&g_S1p[(size_t)(b*128 + c)*4096 + v*64 + h0];
        s0 += w.x; s1 += w.y;
    }
    __shared__ float sr[8][64], se0[64], se1[64];
    sr[ph][h0] = s0; sr[ph][h0+1] = s1;
    if (ph == 0) { se0[h0] = e00; se0[h0+1] = e01; }
    if (ph == 7) { se1[h0] = e10; se1[h0+1] = e11; }
    __syncthreads();
    if (tid < 64) {
        float S = 0.f;
        #pragma unroll
        for (int p = 0; p < 8; p++) S += sr[p][tid];
        int o = b*4096 + v*64 + tid;
        g_S[o]  = S;
        g_E0[o] = se0[tid] + g_E0x1[o];
        g_E1[o] = se1[tid] + g_E1x1[o];
    }
}

// ---------------- K5: collapsed conv+mean --------------------------------------
__global__ void __launch_bounds__(256) k_pool(const float* __restrict__ tw,
                                              const float* __restrict__ tb) {
    int o = blockIdx.x, tid = threadIdx.x;
    float acc[BB];
    #pragma unroll
    for (int b = 0; b < BB; b++) acc[b] = 0.f;
    const float* two = tw + (size_t)o*VH*3;
    for (int i = tid; i < VH; i += 256) {
        float t0 = two[i*3+0], t1 = two[i*3+1], t2 = two[i*3+2];
        float ts = t0 + t1 + t2;
        #pragma unroll
        for (int b = 0; b < BB; b++) {
            int ix = b*VH + i;
            acc[b] += ts*g_S[ix] - t0*g_E1[ix] - t2*g_E0[ix];
        }
    }
    __shared__ float red[16][257];
    __shared__ float red2[16][17];
    #pragma unroll
    for (int b = 0; b < BB; b++) red[b][tid] = acc[b];
    __syncthreads();
    int g = tid >> 4, bq = tid & 15;
    float s = 0.f;
    #pragma unroll
    for (int k = 0; k < 16; k++) s += red[bq][g + k*16];
    red2[bq][g] = s;
    __syncthreads();
    if (tid < 16) {
        float tot = 0.f;
        #pragma unroll
        for (int k = 0; k < 16; k++) tot += red2[tid][k];
        g_y[tid*TC + o] = tot*(1.f/TT) + tb[o];
    }
}

// ---------------- K6: FC head ---------------------------------------------------
__global__ void __launch_bounds__(256) k_fc(const float* __restrict__ f1w,
                                            const float* __restrict__ f1b,
                                            const float* __restrict__ f2w,
                                            const float* __restrict__ f2b,
                                            float* __restrict__ out) {
    __shared__ float ys[BB*TC];
    __shared__ float hs[BB*128];
    int tid = threadIdx.x;
    for (int i = tid; i < BB*TC; i += 256) ys[i] = g_y[i];
    __syncthreads();
    int b = tid >> 4, jq = (tid & 15) * 8;
    float acc[8];
    #pragma unroll
    for (int j = 0; j < 8; j++) acc[j] = f1b[jq+j];
    for (int o = 0; o < TC; o++) {
        float yv = ys[b*TC + o];
        const float* w = f1w + o*128 + jq;
        #pragma unroll
        for (int j = 0; j < 8; j++) acc[j] += yv * w[j];
    }
    #pragma unroll
    for (int j = 0; j < 8; j++) hs[b*128 + jq + j] = fmaxf(acc[j], 0.f);
    __syncthreads();
    if (tid < BB*10) {
        int bb = tid / 10, n = tid % 10;
        float s = f2b[n];
        #pragma unroll 8
        for (int j = 0; j < 128; j++) s += hs[bb*128 + j] * f2w[j*10 + n];
        out[tid] = s;
    }
}

// ---------------- launch ---------------------------------------------------------
extern "C" void kernel_launch(void* const* d_in, const int* in_sizes, int n_in,
                              void* d_out, int out_size) {
    const float* x    = (const float*)d_in[0];
    const float* adj  = (const float*)d_in[1];
    const float* w1   = (const float*)d_in[2];
    const float* g1   = (const float*)d_in[4];
    const float* be1  = (const float*)d_in[5];
    const float* w2   = (const float*)d_in[6];
    const float* g2   = (const float*)d_in[8];
    const float* be2  = (const float*)d_in[9];
    const float* tw   = (const float*)d_in[10];
    const float* tb   = (const float*)d_in[11];
    const float* f1w  = (const float*)d_in[12];
    const float* f1b  = (const float*)d_in[13];
    const float* f2w  = (const float*)d_in[14];
    const float* f2b  = (const float*)d_in[15];
    float* out = (float*)d_out;

    cudaFuncSetAttribute(k_l1, cudaFuncAttributeMaxDynamicSharedMemorySize, L1_SM);
    cudaFuncSetAttribute(k_l2, cudaFuncAttributeMaxDynamicSharedMemorySize, L2_SM);

    k_prep<<<BB, 256>>>(adj, w1, w2);
    k_l1<<<BB*128, 128, L1_SM>>>(x);
    k_stats<<<HH, 256>>>(0, g1, be1);
    k_l2<<<BB*128, 128, L2_SM>>>();
    k_stats<<<HH, 256>>>(1, g2, be2);
    k_sumfinal<<<BB*VV, 256>>>();
    k_pool<<<TC, 256>>>(tw, tb);
    k_fc<<<1, 256>>>(f1w, f1b, f2w, f2b, out);
}

// round 8
// speedup vs baseline: 1.2047x; 1.2047x over previous
#include <cuda_runtime.h>
#include <cuda_bf16.h>
#include <cstdint>

#define BB 16
#define TT 512
#define VV 64
#define HH 64
#define BT (BB*TT)
#define VH (VV*HH)
#define TC 256

// ---------------- scratch ----------------------------------------------------
__device__ __nv_bfloat16 g_adjH[BB*4096], g_adjL[BB*4096]; // swizzled tiles [b][v][w]
__device__ __nv_bfloat16 g_w1H[1024],  g_w1L[1024];        // swizzled [c=16][h=64]
__device__ __nv_bfloat16 g_w2H[4096],  g_w2L[4096];        // swizzled [h][o]
__device__ float g_z1[(size_t)BT*VH];                      // fp32 [bt][v][h]
__device__ __nv_bfloat16 g_z2b[(size_t)BT*VH];             // bf16 [bt][v][o]
__device__ float g_psum1[HH*BT], g_psq1[HH*BT];
__device__ float g_psum2[HH*BT], g_psq2[HH*BT];
__device__ float g_a1[HH], g_c1[HH], g_a2[HH], g_c2[HH];
__device__ float g_S[BB*VH], g_E0[BB*VH], g_E1[BB*VH];
__device__ float g_y[BB*TC];

extern __shared__ unsigned char s_dyn[];

// ---------------- helpers -----------------------------------------------------
__device__ __forceinline__ uint32_t toff(int r, int cB) {
    return (uint32_t)(r*128 + (cB ^ ((r & 7) << 4)));
}
__device__ __forceinline__ int zoff(int r, int c) {
    return r*64 + ((((c >> 2) ^ r) & 15) << 2) + (c & 3);
}
__device__ __forceinline__ void ldsm4(uint32_t* r, unsigned char* p) {
    uint32_t a; asm("{ .reg .u64 t; cvta.to.shared.u64 t, %1; cvt.u32.u64 %0, t; }" : "=r"(a) : "l"(p));
    asm volatile("ldmatrix.sync.aligned.m8n8.x4.shared.b16 {%0,%1,%2,%3}, [%4];"
        : "=r"(r[0]), "=r"(r[1]), "=r"(r[2]), "=r"(r[3]) : "r"(a));
}
__device__ __forceinline__ void ldsm2t(uint32_t& r0, uint32_t& r1, unsigned char* p) {
    uint32_t a; asm("{ .reg .u64 t; cvta.to.shared.u64 t, %1; cvt.u32.u64 %0, t; }" : "=r"(a) : "l"(p));
    asm volatile("ldmatrix.sync.aligned.m8n8.x2.trans.shared.b16 {%0,%1}, [%2];"
        : "=r"(r0), "=r"(r1) : "r"(a));
}
__device__ __forceinline__ void mmabf(float* c, const uint32_t* a, uint32_t b0, uint32_t b1) {
    asm volatile("mma.sync.aligned.m16n8k16.row.col.f32.bf16.bf16.f32 "
        "{%0,%1,%2,%3},{%4,%5,%6,%7},{%8,%9},{%0,%1,%2,%3};"
        : "+f"(c[0]), "+f"(c[1]), "+f"(c[2]), "+f"(c[3])
        : "r"(a[0]), "r"(a[1]), "r"(a[2]), "r"(a[3]), "r"(b0), "r"(b1));
}
__device__ __forceinline__ void split2(float f0, float f1, uint32_t& hi, uint32_t& lo) {
    asm("cvt.rn.bf16x2.f32 %0, %1, %2;" : "=r"(hi) : "f"(f1), "f"(f0));
    float h0 = __uint_as_float(hi << 16);
    float h1 = __uint_as_float(hi & 0xffff0000u);
    asm("cvt.rn.bf16x2.f32 %0, %1, %2;" : "=r"(lo) : "f"(f1 - h1), "f"(f0 - h0));
}
__device__ __forceinline__ uint32_t packbf(float f0, float f1) {
    uint32_t r;
    asm("cvt.rn.bf16x2.f32 %0, %1, %2;" : "=r"(r) : "f"(f1), "f"(f0));
    return r;
}
__device__ __forceinline__ void lda(uint32_t* a, unsigned char* base, int mt, int kt, int lane) {
    int row = mt*16 + (lane & 7) + (lane & 8);
    int cB  = kt*32 + ((lane >> 4) << 4);
    ldsm4(a, base + toff(row, cB));
}
__device__ __forceinline__ void ldb(uint32_t& b0, uint32_t& b1, unsigned char* base, int kt, int nt, int lane) {
    int row = kt*16 + (lane & 15);
    ldsm2t(b0, b1, base + toff(row, nt*16));
}

// ---------------- K0: prep ----------------------------------------------------
__global__ void k_prep(const float* __restrict__ adj, const float* __restrict__ w1,
                       const float* __restrict__ w2) {
    int b = blockIdx.x, tid = threadIdx.x;
    __shared__ float dis[64];
    const float* A = adj + b*4096;
    if (tid < 64) {
        float s = 0.f;
        #pragma unroll 8
        for (int w = 0; w < 64; w++) s += A[tid*64 + w];
        dis[tid] = rsqrtf(s + 1e-6f);
    }
    __syncthreads();
    for (int idx = tid; idx < 4096; idx += 256) {
        int v = idx >> 6, w = idx & 63;
        float a = dis[v] * A[idx] * dis[w];
        __nv_bfloat16 hb = __float2bfloat16(a);
        __nv_bfloat16 lb = __float2bfloat16(a - __bfloat162float(hb));
        uint32_t e = toff(v, w*2) >> 1;
        g_adjH[b*4096 + e] = hb; g_adjL[b*4096 + e] = lb;
    }
    if (b == 0) {
        for (int idx = tid; idx < 1024; idx += 256) {
            int c = idx >> 6, h = idx & 63;
            float val = w1[c*64 + h];
            __nv_bfloat16 hb = __float2bfloat16(val);
            __nv_bfloat16 lb = __float2bfloat16(val - __bfloat162float(hb));
            uint32_t e = toff(c, h*2) >> 1;
            g_w1H[e] = hb; g_w1L[e] = lb;
        }
        for (int idx = tid; idx < 4096; idx += 256) {
            int h = idx >> 6, o = idx & 63;
            float val = w2[h*64 + o];
            __nv_bfloat16 hb = __float2bfloat16(val);
            __nv_bfloat16 lb = __float2bfloat16(val - __bfloat162float(hb));
            uint32_t e = toff(h, o*2) >> 1;
            g_w2H[e] = hb; g_w2L[e] = lb;
        }
    }
}

// ---------------- epilogues ----------------------------------------------------
__device__ __forceinline__ void stage_stats(float acc[4][8][4], float* zs, int lane,
                                            float* psum, float* psq, int bt) {
    #pragma unroll
    for (int mt = 0; mt < 4; mt++)
        #pragma unroll
        for (int nt = 0; nt < 8; nt++) {
            int r = mt*16 + (lane >> 2), c = nt*8 + (lane & 3)*2;
            *(float2*)&zs[zoff(r, c)]   = make_float2(acc[mt][nt][0], acc[mt][nt][1]);
            *(float2*)&zs[zoff(r+8, c)] = make_float2(acc[mt][nt][2], acc[mt][nt][3]);
        }
    __syncwarp();
    float s0 = 0.f, q0 = 0.f, s1 = 0.f, q1 = 0.f;
    #pragma unroll 8
    for (int r = 0; r < 64; r++) {
        float v0 = zs[zoff(r, lane)];
        float v1 = zs[zoff(r, lane + 32)];
        s0 += v0; q0 += v0*v0; s1 += v1; q1 += v1*v1;
    }
    psum[lane*BT + bt] = s0; psum[(lane+32)*BT + bt] = s1;
    psq[lane*BT + bt]  = q0; psq[(lane+32)*BT + bt]  = q1;
}
__device__ __forceinline__ void epilogue_f32(float acc[4][8][4], float* zs, int lane,
                                             float* zout, float* psum, float* psq, int bt) {
    stage_stats(acc, zs, lane, psum, psq, bt);
    #pragma unroll
    for (int it = 0; it < 32; it++) {
        int idx = it*32 + lane;
        int r = idx >> 4, cq = (idx & 15) << 2;
        *(float4*)&zout[r*64 + cq] = *(float4*)&zs[zoff(r, cq)];
    }
}
__device__ __forceinline__ void epilogue_bf(float acc[4][8][4], float* zs, int lane,
                                            __nv_bfloat16* zout, float* psum, float* psq, int bt) {
    stage_stats(acc, zs, lane, psum, psq, bt);
    #pragma unroll
    for (int it = 0; it < 32; it++) {
        int idx = it*32 + lane;
        int r = idx >> 4, cq = (idx & 15) << 2;
        float4 v = *(float4*)&zs[zoff(r, cq)];
        uint32_t p0 = packbf(v.x, v.y), p1 = packbf(v.z, v.w);
        *(uint2*)((unsigned char*)zout + (size_t)(r*64 + cq)*2) = make_uint2(p0, p1);
    }
}

// ---------------- K1: layer1 HMMA ----------------------------------------------
#define L1_WREG 20480
#define L1_SM   (20480 + 4*16384)
__global__ void __launch_bounds__(128, 2) k_l1(const float* __restrict__ x) {
    int blk = blockIdx.x, b = blk >> 7, chunk = blk & 127;
    int tid = threadIdx.x, lane = tid & 31, wq = tid >> 5;
    unsigned char* sm = s_dyn;
    {
        const uint4* s1 = (const uint4*)(g_adjH + b*4096);
        const uint4* s2 = (const uint4*)(g_adjL + b*4096);
        uint4* d1 = (uint4*)sm; uint4* d2 = (uint4*)(sm + 8192);
        for (int i = tid; i < 512; i += 128) { d1[i] = s1[i]; d2[i] = s2[i]; }
        const uint4* s3 = (const uint4*)g_w1H; const uint4* s4 = (const uint4*)g_w1L;
        uint4* d3 = (uint4*)(sm + 16384); uint4* d4 = (uint4*)(sm + 18432);
        if (tid < 128) { d3[tid] = s3[tid]; d4[tid] = s4[tid]; }
    }
    __syncthreads();

    int t = chunk*4 + wq;
    int bt = b*TT + t;
    unsigned char* XH = sm + L1_WREG + wq*16384;
    unsigned char* XL = XH + 8192;
    unsigned char* AH = sm; unsigned char* AL = sm + 8192;
    unsigned char* WH = sm + 16384; unsigned char* WL = sm + 18432;

    const float* xg = x + (size_t)bt*1024;
    #pragma unroll
    for (int it = 0; it < 8; it++) {
        int idx = it*32 + lane;
        int r = idx >> 2, cq = (idx & 3) << 2;
        float4 u = *(const float4*)&xg[r*16 + cq];
        uint32_t h01, l01, h23, l23;
        split2(u.x, u.y, h01, l01); split2(u.z, u.w, h23, l23);
        uint32_t off = toff(r, cq*2);
        *(uint2*)(XH + off) = make_uint2(h01, h23);
        *(uint2*)(XL + off) = make_uint2(l01, l23);
    }
    __syncwarp();

    // GEMM1': tmp[v][c] = sum_w A[v][w] X[w][c]
    float acc1[4][2][4];
    #pragma unroll
    for (int m = 0; m < 4; m++)
        #pragma unroll
        for (int n = 0; n < 2; n++) { acc1[m][n][0]=0; acc1[m][n][1]=0; acc1[m][n][2]=0; acc1[m][n][3]=0; }
    #pragma unroll
    for (int kt = 0; kt < 4; kt++) {
        uint32_t aH[4][4], aL[4][4];
        #pragma unroll
        for (int mt = 0; mt < 4; mt++) { lda(aH[mt], AH, mt, kt, lane); lda(aL[mt], AL, mt, kt, lane); }
        #pragma unroll
        for (int nt = 0; nt < 2; nt++) {
            uint32_t bh0, bh1, bl0, bl1;
            ldb(bh0, bh1, XH, kt, nt, lane);
            ldb(bl0, bl1, XL, kt, nt, lane);
            #pragma unroll
            for (int mt = 0; mt < 4; mt++) {
                mmabf(acc1[mt][nt], aH[mt], bh0, bh1);
                mmabf(acc1[mt][nt], aL[mt], bh0, bh1);
                mmabf(acc1[mt][nt], aH[mt], bl0, bl1);
            }
        }
    }
    __syncwarp();
    #pragma unroll
    for (int mt = 0; mt < 4; mt++)
        #pragma unroll
        for (int nt = 0; nt < 2; nt++) {
            int r = mt*16 + (lane >> 2), cB = (nt*8 + (lane & 3)*2)*2;
            uint32_t h, l;
            split2(acc1[mt][nt][0], acc1[mt][nt][1], h, l);
            *(uint32_t*)(XH + toff(r, cB)) = h; *(uint32_t*)(XL + toff(r, cB)) = l;
            split2(acc1[mt][nt][2], acc1[mt][nt][3], h, l);
            *(uint32_t*)(XH + toff(r+8, cB)) = h; *(uint32_t*)(XL + toff(r+8, cB)) = l;
        }
    __syncwarp();

    // GEMM2': z1[v][h] = sum_c tmp[v][c] W1[c][h]
    float acc2[4][8][4];
    #pragma unroll
    for (int m = 0; m < 4; m++)
        #pragma unroll
        for (int n = 0; n < 8; n++) { acc2[m][n][0]=0; acc2[m][n][1]=0; acc2[m][n][2]=0; acc2[m][n][3]=0; }
    {
        uint32_t aH[4][4], aL[4][4];
        #pragma unroll
        for (int mt = 0; mt < 4; mt++) { lda(aH[mt], XH, mt, 0, lane); lda(aL[mt], XL, mt, 0, lane); }
        #pragma unroll
        for (int nt = 0; nt < 8; nt++) {
            uint32_t bh0, bh1, bl0, bl1;
            ldb(bh0, bh1, WH, 0, nt, lane);
            ldb(bl0, bl1, WL, 0, nt, lane);
            #pragma unroll
            for (int mt = 0; mt < 4; mt++) {
                mmabf(acc2[mt][nt], aH[mt], bh0, bh1);
                mmabf(acc2[mt][nt], aL[mt], bh0, bh1);
                mmabf(acc2[mt][nt], aH[mt], bl0, bl1);
            }
        }
    }
    __syncwarp();
    epilogue_f32(acc2, (float*)XH, lane, g_z1 + (size_t)bt*4096, g_psum1, g_psq1, bt);
}

// ---------------- K2: finalize BN affine ---------------------------------------
__global__ void k_stats(int layer, const float* __restrict__ g, const float* __restrict__ be) {
    int h = blockIdx.x, tid = threadIdx.x;
    const float* ps = layer ? g_psum2 : g_psum1;
    const float* pq = layer ? g_psq2  : g_psq1;
    __shared__ float ss[256], sq[256];
    float s = 0.f, q = 0.f;
    for (int i = tid; i < BT; i += 256) { s += ps[h*BT + i]; q += pq[h*BT + i]; }
    ss[tid] = s; sq[tid] = q;
    __syncthreads();
    for (int st = 128; st > 0; st >>= 1) {
        if (tid < st) { ss[tid] += ss[tid+st]; sq[tid] += sq[tid+st]; }
        __syncthreads();
    }
    if (tid == 0) {
        const float N = (float)(BT*VV);
        float mean = ss[0] / N;
        float var  = sq[0] / N - mean*mean;
        float av = g[h] * rsqrtf(var + 1e-5f);
        if (layer) { g_a2[h] = av; g_c2[h] = be[h] - mean*av; }
        else       { g_a1[h] = av; g_c1[h] = be[h] - mean*av; }
    }
}

// ---------------- K3: layer2 HMMA (round-6 barrier-free form) -------------------
#define L2_WREG 33280
#define L2_SM   (33280 + 4*16384)
__global__ void __launch_bounds__(128, 2) k_l2() {
    int blk = blockIdx.x, b = blk >> 7, chunk = blk & 127;
    int tid = threadIdx.x, lane = tid & 31, wq = tid >> 5;
    unsigned char* sm = s_dyn;
    float* a1s = (float*)(sm + 32768);
    float* c1s = a1s + 64;
    {
        const uint4* s1 = (const uint4*)(g_adjH + b*4096);
        const uint4* s2 = (const uint4*)(g_adjL + b*4096);
        uint4* d1 = (uint4*)sm; uint4* d2 = (uint4*)(sm + 8192);
        for (int i = tid; i < 512; i += 128) { d1[i] = s1[i]; d2[i] = s2[i]; }
        const uint4* s3 = (const uint4*)g_w2H; const uint4* s4 = (const uint4*)g_w2L;
        uint4* d3 = (uint4*)(sm + 16384); uint4* d4 = (uint4*)(sm + 24576);
        for (int i = tid; i < 512; i += 128) { d3[i] = s3[i]; d4[i] = s4[i]; }
        if (tid < 64) { a1s[tid] = g_a1[tid]; c1s[tid] = g_c1[tid]; }
    }
    __syncthreads();

    int t = chunk*4 + wq;
    int bt = b*TT + t;
    unsigned char* XH = sm + L2_WREG + wq*16384;
    unsigned char* XL = XH + 8192;
    unsigned char* AH = sm; unsigned char* AL = sm + 8192;
    unsigned char* WH = sm + 16384; unsigned char* WL = sm + 24576;

    // build x1 tile [w=64][h=64] = relu(a1*z1+c1), bf16 hi/lo
    const float* zt = g_z1 + (size_t)bt*4096;
    #pragma unroll
    for (int it = 0; it < 32; it++) {
        int idx = it*32 + lane;
        int r = idx >> 4, cq = (idx & 15) << 2;
        float4 u = *(const float4*)&zt[r*64 + cq];
        float4 av = *(float4*)&a1s[cq];
        float4 cv = *(float4*)&c1s[cq];
        float e0 = fmaxf(fmaf(u.x, av.x, cv.x), 0.f);
        float e1 = fmaxf(fmaf(u.y, av.y, cv.y), 0.f);
        float e2 = fmaxf(fmaf(u.z, av.z, cv.z), 0.f);
        float e3 = fmaxf(fmaf(u.w, av.w, cv.w), 0.f);
        uint32_t h01, l01, h23, l23;
        split2(e0, e1, h01, l01); split2(e2, e3, h23, l23);
        uint32_t off = toff(r, cq*2);
        *(uint2*)(XH + off) = make_uint2(h01, h23);
        *(uint2*)(XL + off) = make_uint2(l01, l23);
    }
    __syncwarp();

    float acc[4][8][4];
    #pragma unroll
    for (int m = 0; m < 4; m++)
        #pragma unroll
        for (int n = 0; n < 8; n++) { acc[m][n][0]=0; acc[m][n][1]=0; acc[m][n][2]=0; acc[m][n][3]=0; }

    // GEMM1: tmp[v][h] = sum_w A[v][w] x1[w][h]
    #pragma unroll
    for (int kt = 0; kt < 4; kt++) {
        uint32_t aH[4][4], aL[4][4];
        #pragma unroll
        for (int mt = 0; mt < 4; mt++) { lda(aH[mt], AH, mt, kt, lane); lda(aL[mt], AL, mt, kt, lane); }
        #pragma unroll
        for (int nt = 0; nt < 8; nt++) {
            uint32_t bh0, bh1, bl0, bl1;
            ldb(bh0, bh1, XH, kt, nt, lane);
            ldb(bl0, bl1, XL, kt, nt, lane);
            #pragma unroll
            for (int mt = 0; mt < 4; mt++) {
                mmabf(acc[mt][nt], aH[mt], bh0, bh1);
                mmabf(acc[mt][nt], aL[mt], bh0, bh1);
                mmabf(acc[mt][nt], aH[mt], bl0, bl1);
            }
        }
    }
    __syncwarp();
    #pragma unroll
    for (int mt = 0; mt < 4; mt++)
        #pragma unroll
        for (int nt = 0; nt < 8; nt++) {
            int r = mt*16 + (lane >> 2), cB = (nt*8 + (lane & 3)*2)*2;
            uint32_t h, l;
            split2(acc[mt][nt][0], acc[mt][nt][1], h, l);
            *(uint32_t*)(XH + toff(r, cB)) = h; *(uint32_t*)(XL + toff(r, cB)) = l;
            split2(acc[mt][nt][2], acc[mt][nt][3], h, l);
            *(uint32_t*)(XH + toff(r+8, cB)) = h; *(uint32_t*)(XL + toff(r+8, cB)) = l;
        }
    __syncwarp();

    // GEMM2: z2[v][o] = sum_h tmp[v][h] W2[h][o]
    #pragma unroll
    for (int m = 0; m < 4; m++)
        #pragma unroll
        for (int n = 0; n < 8; n++) { acc[m][n][0]=0; acc[m][n][1]=0; acc[m][n][2]=0; acc[m][n][3]=0; }
    #pragma unroll
    for (int kt = 0; kt < 4; kt++) {
        uint32_t aH[4][4], aL[4][4];
        #pragma unroll
        for (int mt = 0; mt < 4; mt++) { lda(aH[mt], XH, mt, kt, lane); lda(aL[mt], XL, mt, kt, lane); }
        #pragma unroll
        for (int nt = 0; nt < 8; nt++) {
            uint32_t bh0, bh1, bl0, bl1;
            ldb(bh0, bh1, WH, kt, nt, lane);
            ldb(bl0, bl1, WL, kt, nt, lane);
            #pragma unroll
            for (int mt = 0; mt < 4; mt++) {
                mmabf(acc[mt][nt], aH[mt], bh0, bh1);
                mmabf(acc[mt][nt], aL[mt], bh0, bh1);
                mmabf(acc[mt][nt], aH[mt], bl0, bl1);
            }
        }
    }
    __syncwarp();
    epilogue_bf(acc, (float*)XH, lane, g_z2b + (size_t)bt*4096, g_psum2, g_psq2, bt);
}

// ---------------- K4: S = sum_t [relu(BN1(z1)) + relu(BN2(z2))]; edges ---------
__global__ void __launch_bounds__(256) k_sumfinal() {
    int bv = blockIdx.x, b = bv >> 6, v = bv & 63;
    int tid = threadIdx.x;
    int hq = (tid & 15) << 2, ph = tid >> 4;     // 16 h-quads x 16 t-phases
    float4 A1 = *(float4*)&g_a1[hq], C1 = *(float4*)&g_c1[hq];
    float4 A2 = *(float4*)&g_a2[hq], C2 = *(float4*)&g_c2[hq];
    const uint32_t* zp = (const uint32_t*)g_z2b;
    float4 s = make_float4(0.f,0.f,0.f,0.f);
    float4 e0 = s, e1 = s;
    #pragma unroll 4
    for (int t = ph; t < TT; t += 16) {
        size_t i1 = (((size_t)(b*TT + t))*64 + v)*64 + hq;
        float4 z = *(const float4*)&g_z1[i1];
        uint2 u = *(const uint2*)&zp[i1 >> 1];
        float x0 = fmaxf(fmaf(z.x, A1.x, C1.x), 0.f)
                 + fmaxf(fmaf(__uint_as_float(u.x << 16),        A2.x, C2.x), 0.f);
        float x1 = fmaxf(fmaf(z.y, A1.y, C1.y), 0.f)
                 + fmaxf(fmaf(__uint_as_float(u.x & 0xffff0000u), A2.y, C2.y), 0.f);
        float x2 = fmaxf(fmaf(z.z, A1.z, C1.z), 0.f)
                 + fmaxf(fmaf(__uint_as_float(u.y << 16),        A2.z, C2.z), 0.f);
        float x3 = fmaxf(fmaf(z.w, A1.w, C1.w), 0.f)
                 + fmaxf(fmaf(__uint_as_float(u.y & 0xffff0000u), A2.w, C2.w), 0.f);
        s.x += x0; s.y += x1; s.z += x2; s.w += x3;
        if (t == 0)    e0 = make_float4(x0, x1, x2, x3);
        if (t == TT-1) e1 = make_float4(x0, x1, x2, x3);
    }
    __shared__ float sr[16][64], se0[64], se1[64];
    *(float4*)&sr[ph][hq] = s;
    if (ph == 0)  *(float4*)&se0[hq] = e0;
    if (ph == 15) *(float4*)&se1[hq] = e1;
    __syncthreads();
    if (tid < 64) {
        float S = 0.f;
        #pragma unroll
        for (int p = 0; p < 16; p++) S += sr[p][tid];
        int o = b*4096 + v*64 + tid;
        g_S[o]  = S;
        g_E0[o] = se0[tid];
        g_E1[o] = se1[tid];
    }
}

// ---------------- K5: collapsed conv+mean --------------------------------------
__global__ void __launch_bounds__(256) k_pool(const float* __restrict__ tw,
                                              const float* __restrict__ tb) {
    int o = blockIdx.x, tid = threadIdx.x;
    float acc[BB];
    #pragma unroll
    for (int b = 0; b < BB; b++) acc[b] = 0.f;
    const float* two = tw + (size_t)o*VH*3;
    for (int i = tid; i < VH; i += 256) {
        float t0 = two[i*3+0], t1 = two[i*3+1], t2 = two[i*3+2];
        float ts = t0 + t1 + t2;
        #pragma unroll
        for (int b = 0; b < BB; b++) {
            int ix = b*VH + i;
            acc[b] += ts*g_S[ix] - t0*g_E1[ix] - t2*g_E0[ix];
        }
    }
    __shared__ float red[16][257];
    __shared__ float red2[16][17];
    #pragma unroll
    for (int b = 0; b < BB; b++) red[b][tid] = acc[b];
    __syncthreads();
    int g = tid >> 4, bq = tid & 15;
    float s = 0.f;
    #pragma unroll
    for (int k = 0; k < 16; k++) s += red[bq][g + k*16];
    red2[bq][g] = s;
    __syncthreads();
    if (tid < 16) {
        float tot = 0.f;
        #pragma unroll
        for (int k = 0; k < 16; k++) tot += red2[tid][k];
        g_y[tid*TC + o] = tot*(1.f/TT) + tb[o];
    }
}

// ---------------- K6: FC head ---------------------------------------------------
__global__ void __launch_bounds__(256) k_fc(const float* __restrict__ f1w,
                                            const float* __restrict__ f1b,
                                            const float* __restrict__ f2w,
                                            const float* __restrict__ f2b,
                                            float* __restrict__ out) {
    __shared__ float ys[BB*TC];
    __shared__ float hs[BB*128];
    int tid = threadIdx.x;
    for (int i = tid; i < BB*TC; i += 256) ys[i] = g_y[i];
    __syncthreads();
    int b = tid >> 4, jq = (tid & 15) * 8;
    float acc[8];
    #pragma unroll
    for (int j = 0; j < 8; j++) acc[j] = f1b[jq+j];
    for (int o = 0; o < TC; o++) {
        float yv = ys[b*TC + o];
        const float* w = f1w + o*128 + jq;
        #pragma unroll
        for (int j = 0; j < 8; j++) acc[j] += yv * w[j];
    }
    #pragma unroll
    for (int j = 0; j < 8; j++) hs[b*128 + jq + j] = fmaxf(acc[j], 0.f);
    __syncthreads();
    if (tid < BB*10) {
        int bb = tid / 10, n = tid % 10;
        float s = f2b[n];
        #pragma unroll 8
        for (int j = 0; j < 128; j++) s += hs[bb*128 + j] * f2w[j*10 + n];
        out[tid] = s;
    }
}

// ---------------- launch ---------------------------------------------------------
extern "C" void kernel_launch(void* const* d_in, const int* in_sizes, int n_in,
                              void* d_out, int out_size) {
    const float* x    = (const float*)d_in[0];
    const float* adj  = (const float*)d_in[1];
    const float* w1   = (const float*)d_in[2];
    const float* g1   = (const float*)d_in[4];
    const float* be1  = (const float*)d_in[5];
    const float* w2   = (const float*)d_in[6];
    const float* g2   = (const float*)d_in[8];
    const float* be2  = (const float*)d_in[9];
    const float* tw   = (const float*)d_in[10];
    const float* tb   = (const float*)d_in[11];
    const float* f1w  = (const float*)d_in[12];
    const float* f1b  = (const float*)d_in[13];
    const float* f2w  = (const float*)d_in[14];
    const float* f2b  = (const float*)d_in[15];
    float* out = (float*)d_out;

    cudaFuncSetAttribute(k_l1, cudaFuncAttributeMaxDynamicSharedMemorySize, L1_SM);
    cudaFuncSetAttribute(k_l2, cudaFuncAttributeMaxDynamicSharedMemorySize, L2_SM);

    k_prep<<<BB, 256>>>(adj, w1, w2);
    k_l1<<<BB*128, 128, L1_SM>>>(x);
    k_stats<<<HH, 256>>>(0, g1, be1);
    k_l2<<<BB*128, 128, L2_SM>>>();
    k_stats<<<HH, 256>>>(1, g2, be2);
    k_sumfinal<<<BB*VV, 256>>>();
    k_pool<<<TC, 256>>>(tw, tb);
    k_fc<<<1, 256>>>(f1w, f1b, f2w, f2b, out);
}

// round 9
// speedup vs baseline: 1.3777x; 1.1436x over previous
#include <cuda_runtime.h>
#include <cuda_bf16.h>
#include <cstdint>

#define BB 16
#define TT 512
#define VV 64
#define HH 64
#define BT (BB*TT)
#define VH (VV*HH)
#define TC 256

// ---------------- scratch ----------------------------------------------------
__device__ __nv_bfloat16 g_adjH[BB*4096], g_adjL[BB*4096]; // swizzled tiles [b][v][w]
__device__ __nv_bfloat16 g_w1H[1024];                      // swizzled [c=16][h=64]
__device__ __nv_bfloat16 g_w2H[4096],  g_w2L[4096];        // swizzled [h][o]
__device__ __nv_bfloat16 g_z1b[(size_t)BT*VH];             // bf16 [bt][v][h]
__device__ __nv_bfloat16 g_z2b[(size_t)BT*VH];             // bf16 [bt][v][o]
__device__ float g_psum1[HH*BT], g_psq1[HH*BT];
__device__ float g_psum2[HH*BT], g_psq2[HH*BT];
__device__ float g_a1[HH], g_c1[HH], g_a2[HH], g_c2[HH];
__device__ float g_S[BB*VH], g_E0[BB*VH], g_E1[BB*VH];
__device__ float g_y[BB*TC];

extern __shared__ unsigned char s_dyn[];

// ---------------- helpers -----------------------------------------------------
__device__ __forceinline__ uint32_t toff(int r, int cB) {
    return (uint32_t)(r*128 + (cB ^ ((r & 7) << 4)));
}
__device__ __forceinline__ int zoff(int r, int c) {
    return r*64 + ((((c >> 2) ^ r) & 15) << 2) + (c & 3);
}
__device__ __forceinline__ void ldsm4(uint32_t* r, unsigned char* p) {
    uint32_t a; asm("{ .reg .u64 t; cvta.to.shared.u64 t, %1; cvt.u32.u64 %0, t; }" : "=r"(a) : "l"(p));
    asm volatile("ldmatrix.sync.aligned.m8n8.x4.shared.b16 {%0,%1,%2,%3}, [%4];"
        : "=r"(r[0]), "=r"(r[1]), "=r"(r[2]), "=r"(r[3]) : "r"(a));
}
__device__ __forceinline__ void ldsm2t(uint32_t& r0, uint32_t& r1, unsigned char* p) {
    uint32_t a; asm("{ .reg .u64 t; cvta.to.shared.u64 t, %1; cvt.u32.u64 %0, t; }" : "=r"(a) : "l"(p));
    asm volatile("ldmatrix.sync.aligned.m8n8.x2.trans.shared.b16 {%0,%1}, [%2];"
        : "=r"(r0), "=r"(r1) : "r"(a));
}
__device__ __forceinline__ void mmabf(float* c, const uint32_t* a, uint32_t b0, uint32_t b1) {
    asm volatile("mma.sync.aligned.m16n8k16.row.col.f32.bf16.bf16.f32 "
        "{%0,%1,%2,%3},{%4,%5,%6,%7},{%8,%9},{%0,%1,%2,%3};"
        : "+f"(c[0]), "+f"(c[1]), "+f"(c[2]), "+f"(c[3])
        : "r"(a[0]), "r"(a[1]), "r"(a[2]), "r"(a[3]), "r"(b0), "r"(b1));
}
__device__ __forceinline__ void split2(float f0, float f1, uint32_t& hi, uint32_t& lo) {
    asm("cvt.rn.bf16x2.f32 %0, %1, %2;" : "=r"(hi) : "f"(f1), "f"(f0));
    float h0 = __uint_as_float(hi << 16);
    float h1 = __uint_as_float(hi & 0xffff0000u);
    asm("cvt.rn.bf16x2.f32 %0, %1, %2;" : "=r"(lo) : "f"(f1 - h1), "f"(f0 - h0));
}
__device__ __forceinline__ uint32_t packbf(float f0, float f1) {
    uint32_t r;
    asm("cvt.rn.bf16x2.f32 %0, %1, %2;" : "=r"(r) : "f"(f1), "f"(f0));
    return r;
}
__device__ __forceinline__ void lda(uint32_t* a, unsigned char* base, int mt, int kt, int lane) {
    int row = mt*16 + (lane & 7) + (lane & 8);
    int cB  = kt*32 + ((lane >> 4) << 4);
    ldsm4(a, base + toff(row, cB));
}
__device__ __forceinline__ void ldb(uint32_t& b0, uint32_t& b1, unsigned char* base, int kt, int nt, int lane) {
    int row = kt*16 + (lane & 15);
    ldsm2t(b0, b1, base + toff(row, nt*16));
}

// ---------------- K0: prep ----------------------------------------------------
__global__ void k_prep(const float* __restrict__ adj, const float* __restrict__ w1,
                       const float* __restrict__ w2) {
    int b = blockIdx.x, tid = threadIdx.x;
    __shared__ float dis[64];
    const float* A = adj + b*4096;
    if (tid < 64) {
        float s = 0.f;
        #pragma unroll 8
        for (int w = 0; w < 64; w++) s += A[tid*64 + w];
        dis[tid] = rsqrtf(s + 1e-6f);
    }
    __syncthreads();
    for (int idx = tid; idx < 4096; idx += 256) {
        int v = idx >> 6, w = idx & 63;
        float a = dis[v] * A[idx] * dis[w];
        __nv_bfloat16 hb = __float2bfloat16(a);
        __nv_bfloat16 lb = __float2bfloat16(a - __bfloat162float(hb));
        uint32_t e = toff(v, w*2) >> 1;
        g_adjH[b*4096 + e] = hb; g_adjL[b*4096 + e] = lb;
    }
    if (b == 0) {
        for (int idx = tid; idx < 1024; idx += 256) {
            int c = idx >> 6, h = idx & 63;
            uint32_t e = toff(c, h*2) >> 1;
            g_w1H[e] = __float2bfloat16(w1[c*64 + h]);
        }
        for (int idx = tid; idx < 4096; idx += 256) {
            int h = idx >> 6, o = idx & 63;
            float val = w2[h*64 + o];
            __nv_bfloat16 hb = __float2bfloat16(val);
            __nv_bfloat16 lb = __float2bfloat16(val - __bfloat162float(hb));
            uint32_t e = toff(h, o*2) >> 1;
            g_w2H[e] = hb; g_w2L[e] = lb;
        }
    }
}

// ---------------- epilogue: stage acc -> swizzled fp32, stats, bf16 store ------
__device__ __forceinline__ void epilogue_bf(float acc[4][8][4], float* zs, int lane,
                                            __nv_bfloat16* zout, float* psum, float* psq, int bt) {
    #pragma unroll
    for (int mt = 0; mt < 4; mt++)
        #pragma unroll
        for (int nt = 0; nt < 8; nt++) {
            int r = mt*16 + (lane >> 2), c = nt*8 + (lane & 3)*2;
            *(float2*)&zs[zoff(r, c)]   = make_float2(acc[mt][nt][0], acc[mt][nt][1]);
            *(float2*)&zs[zoff(r+8, c)] = make_float2(acc[mt][nt][2], acc[mt][nt][3]);
        }
    __syncwarp();
    float s0 = 0.f, q0 = 0.f, s1 = 0.f, q1 = 0.f;
    #pragma unroll 8
    for (int r = 0; r < 64; r++) {
        float v0 = zs[zoff(r, lane)];
        float v1 = zs[zoff(r, lane + 32)];
        s0 += v0; q0 += v0*v0; s1 += v1; q1 += v1*v1;
    }
    psum[lane*BT + bt] = s0; psum[(lane+32)*BT + bt] = s1;
    psq[lane*BT + bt]  = q0; psq[(lane+32)*BT + bt]  = q1;
    #pragma unroll
    for (int it = 0; it < 32; it++) {
        int idx = it*32 + lane;
        int r = idx >> 4, cq = (idx & 15) << 2;
        float4 v = *(float4*)&zs[zoff(r, cq)];
        uint32_t p0 = packbf(v.x, v.y), p1 = packbf(v.z, v.w);
        *(uint2*)((unsigned char*)zout + (size_t)(r*64 + cq)*2) = make_uint2(p0, p1);
    }
}

// ---------------- K1: layer1 HMMA (2-term compensation) -------------------------
#define L1_WREG 20480
#define L1_SM   (20480 + 4*16384)
__global__ void __launch_bounds__(128, 2) k_l1(const float* __restrict__ x) {
    int blk = blockIdx.x, b = blk >> 7, chunk = blk & 127;
    int tid = threadIdx.x, lane = tid & 31, wq = tid >> 5;
    unsigned char* sm = s_dyn;
    {
        const uint4* s1 = (const uint4*)(g_adjH + b*4096);
        const uint4* s2 = (const uint4*)(g_adjL + b*4096);
        uint4* d1 = (uint4*)sm; uint4* d2 = (uint4*)(sm + 8192);
        for (int i = tid; i < 512; i += 128) { d1[i] = s1[i]; d2[i] = s2[i]; }
        const uint4* s3 = (const uint4*)g_w1H;
        uint4* d3 = (uint4*)(sm + 16384);
        if (tid < 128) d3[tid] = s3[tid];
    }
    __syncthreads();

    int t = chunk*4 + wq;
    int bt = b*TT + t;
    unsigned char* XH = sm + L1_WREG + wq*16384;
    unsigned char* XL = XH + 8192;
    unsigned char* AH = sm; unsigned char* AL = sm + 8192;
    unsigned char* WH = sm + 16384;

    // build X tile [w=64][c=16] bf16 (hi only)
    const float* xg = x + (size_t)bt*1024;
    #pragma unroll
    for (int it = 0; it < 8; it++) {
        int idx = it*32 + lane;
        int r = idx >> 2, cq = (idx & 3) << 2;
        float4 u = *(const float4*)&xg[r*16 + cq];
        *(uint2*)(XH + toff(r, cq*2)) = make_uint2(packbf(u.x, u.y), packbf(u.z, u.w));
    }
    __syncwarp();

    // GEMM1': tmp[v][c] = sum_w A[v][w] X[w][c]  (A hi/lo x X hi)
    float acc1[4][2][4];
    #pragma unroll
    for (int m = 0; m < 4; m++)
        #pragma unroll
        for (int n = 0; n < 2; n++) { acc1[m][n][0]=0; acc1[m][n][1]=0; acc1[m][n][2]=0; acc1[m][n][3]=0; }
    #pragma unroll
    for (int kt = 0; kt < 4; kt++) {
        uint32_t aH[4][4], aL[4][4];
        #pragma unroll
        for (int mt = 0; mt < 4; mt++) { lda(aH[mt], AH, mt, kt, lane); lda(aL[mt], AL, mt, kt, lane); }
        #pragma unroll
        for (int nt = 0; nt < 2; nt++) {
            uint32_t bh0, bh1;
            ldb(bh0, bh1, XH, kt, nt, lane);
            #pragma unroll
            for (int mt = 0; mt < 4; mt++) {
                mmabf(acc1[mt][nt], aH[mt], bh0, bh1);
                mmabf(acc1[mt][nt], aL[mt], bh0, bh1);
            }
        }
    }
    __syncwarp();
    // store tmp hi/lo
    #pragma unroll
    for (int mt = 0; mt < 4; mt++)
        #pragma unroll
        for (int nt = 0; nt < 2; nt++) {
            int r = mt*16 + (lane >> 2), cB = (nt*8 + (lane & 3)*2)*2;
            uint32_t h, l;
            split2(acc1[mt][nt][0], acc1[mt][nt][1], h, l);
            *(uint32_t*)(XH + toff(r, cB)) = h; *(uint32_t*)(XL + toff(r, cB)) = l;
            split2(acc1[mt][nt][2], acc1[mt][nt][3], h, l);
            *(uint32_t*)(XH + toff(r+8, cB)) = h; *(uint32_t*)(XL + toff(r+8, cB)) = l;
        }
    __syncwarp();

    // GEMM2': z1[v][h] = sum_c tmp[v][c] W1[c][h]  (tmp hi/lo x W1 hi)
    float acc2[4][8][4];
    #pragma unroll
    for (int m = 0; m < 4; m++)
        #pragma unroll
        for (int n = 0; n < 8; n++) { acc2[m][n][0]=0; acc2[m][n][1]=0; acc2[m][n][2]=0; acc2[m][n][3]=0; }
    {
        uint32_t aH[4][4], aL[4][4];
        #pragma unroll
        for (int mt = 0; mt < 4; mt++) { lda(aH[mt], XH, mt, 0, lane); lda(aL[mt], XL, mt, 0, lane); }
        #pragma unroll
        for (int nt = 0; nt < 8; nt++) {
            uint32_t bh0, bh1;
            ldb(bh0, bh1, WH, 0, nt, lane);
            #pragma unroll
            for (int mt = 0; mt < 4; mt++) {
                mmabf(acc2[mt][nt], aH[mt], bh0, bh1);
                mmabf(acc2[mt][nt], aL[mt], bh0, bh1);
            }
        }
    }
    __syncwarp();
    epilogue_bf(acc2, (float*)XH, lane, g_z1b + (size_t)bt*4096, g_psum1, g_psq1, bt);
}

// ---------------- K2: finalize BN affine ---------------------------------------
__global__ void k_stats(int layer, const float* __restrict__ g, const float* __restrict__ be) {
    int h = blockIdx.x, tid = threadIdx.x;
    const float* ps = layer ? g_psum2 : g_psum1;
    const float* pq = layer ? g_psq2  : g_psq1;
    __shared__ float ss[256], sq[256];
    float s = 0.f, q = 0.f;
    for (int i = tid; i < BT; i += 256) { s += ps[h*BT + i]; q += pq[h*BT + i]; }
    ss[tid] = s; sq[tid] = q;
    __syncthreads();
    for (int st = 128; st > 0; st >>= 1) {
        if (tid < st) { ss[tid] += ss[tid+st]; sq[tid] += sq[tid+st]; }
        __syncthreads();
    }
    if (tid == 0) {
        const float N = (float)(BT*VV);
        float mean = ss[0] / N;
        float var  = sq[0] / N - mean*mean;
        float av = g[h] * rsqrtf(var + 1e-5f);
        if (layer) { g_a2[h] = av; g_c2[h] = be[h] - mean*av; }
        else       { g_a1[h] = av; g_c1[h] = be[h] - mean*av; }
    }
}

// ---------------- K3: layer2 HMMA ----------------------------------------------
#define L2_WREG 33280
#define L2_SM   (33280 + 4*16384)
__global__ void __launch_bounds__(128, 2) k_l2() {
    int blk = blockIdx.x, b = blk >> 7, chunk = blk & 127;
    int tid = threadIdx.x, lane = tid & 31, wq = tid >> 5;
    unsigned char* sm = s_dyn;
    float* a1s = (float*)(sm + 32768);
    float* c1s = a1s + 64;
    {
        const uint4* s1 = (const uint4*)(g_adjH + b*4096);
        const uint4* s2 = (const uint4*)(g_adjL + b*4096);
        uint4* d1 = (uint4*)sm; uint4* d2 = (uint4*)(sm + 8192);
        for (int i = tid; i < 512; i += 128) { d1[i] = s1[i]; d2[i] = s2[i]; }
        const uint4* s3 = (const uint4*)g_w2H; const uint4* s4 = (const uint4*)g_w2L;
        uint4* d3 = (uint4*)(sm + 16384); uint4* d4 = (uint4*)(sm + 24576);
        for (int i = tid; i < 512; i += 128) { d3[i] = s3[i]; d4[i] = s4[i]; }
        if (tid < 64) { a1s[tid] = g_a1[tid]; c1s[tid] = g_c1[tid]; }
    }
    __syncthreads();

    int t = chunk*4 + wq;
    int bt = b*TT + t;
    unsigned char* XH = sm + L2_WREG + wq*16384;
    unsigned char* XL = XH + 8192;
    unsigned char* AH = sm; unsigned char* AL = sm + 8192;
    unsigned char* WH = sm + 16384; unsigned char* WL = sm + 24576;

    // build x1 tile [w=64][h=64] = relu(a1*z1+c1) from bf16 z1, hi only
    const unsigned char* ztb = (const unsigned char*)(g_z1b + (size_t)bt*4096);
    #pragma unroll
    for (int it = 0; it < 32; it++) {
        int idx = it*32 + lane;
        int r = idx >> 4, cq = (idx & 15) << 2;
        uint2 u = *(const uint2*)(ztb + (r*64 + cq)*2);
        float4 av = *(float4*)&a1s[cq];
        float4 cv = *(float4*)&c1s[cq];
        float e0 = fmaxf(fmaf(__uint_as_float(u.x << 16),         av.x, cv.x), 0.f);
        float e1 = fmaxf(fmaf(__uint_as_float(u.x & 0xffff0000u), av.y, cv.y), 0.f);
        float e2 = fmaxf(fmaf(__uint_as_float(u.y << 16),         av.z, cv.z), 0.f);
        float e3 = fmaxf(fmaf(__uint_as_float(u.y & 0xffff0000u), av.w, cv.w), 0.f);
        *(uint2*)(XH + toff(r, cq*2)) = make_uint2(packbf(e0, e1), packbf(e2, e3));
    }
    __syncwarp();

    float acc[4][8][4];
    #pragma unroll
    for (int m = 0; m < 4; m++)
        #pragma unroll
        for (int n = 0; n < 8; n++) { acc[m][n][0]=0; acc[m][n][1]=0; acc[m][n][2]=0; acc[m][n][3]=0; }

    // GEMM1: tmp[v][h] = sum_w A[v][w] x1[w][h]  (A hi/lo x x1 hi)
    #pragma unroll
    for (int kt = 0; kt < 4; kt++) {
        uint32_t aH[4][4], aL[4][4];
        #pragma unroll
        for (int mt = 0; mt < 4; mt++) { lda(aH[mt], AH, mt, kt, lane); lda(aL[mt], AL, mt, kt, lane); }
        #pragma unroll
        for (int nt = 0; nt < 8; nt++) {
            uint32_t bh0, bh1;
            ldb(bh0, bh1, XH, kt, nt, lane);
            #pragma unroll
            for (int mt = 0; mt < 4; mt++) {
                mmabf(acc[mt][nt], aH[mt], bh0, bh1);
                mmabf(acc[mt][nt], aL[mt], bh0, bh1);
            }
        }
    }
    __syncwarp();
    #pragma unroll
    for (int mt = 0; mt < 4; mt++)
        #pragma unroll
        for (int nt = 0; nt < 8; nt++) {
            int r = mt*16 + (lane >> 2), cB = (nt*8 + (lane & 3)*2)*2;
            uint32_t h, l;
            split2(acc[mt][nt][0], acc[mt][nt][1], h, l);
            *(uint32_t*)(XH + toff(r, cB)) = h; *(uint32_t*)(XL + toff(r, cB)) = l;
            split2(acc[mt][nt][2], acc[mt][nt][3], h, l);
            *(uint32_t*)(XH + toff(r+8, cB)) = h; *(uint32_t*)(XL + toff(r+8, cB)) = l;
        }
    __syncwarp();

    // GEMM2: z2[v][o] = sum_h tmp[v][h] W2[h][o]  (3-term: tmpH*WH + tmpL*WH + tmpH*WL)
    #pragma unroll
    for (int m = 0; m < 4; m++)
        #pragma unroll
        for (int n = 0; n < 8; n++) { acc[m][n][0]=0; acc[m][n][1]=0; acc[m][n][2]=0; acc[m][n][3]=0; }
    #pragma unroll
    for (int kt = 0; kt < 4; kt++) {
        uint32_t aH[4][4], aL[4][4];
        #pragma unroll
        for (int mt = 0; mt < 4; mt++) { lda(aH[mt], XH, mt, kt, lane); lda(aL[mt], XL, mt, kt, lane); }
        #pragma unroll
        for (int nt = 0; nt < 8; nt++) {
            uint32_t bh0, bh1, bl0, bl1;
            ldb(bh0, bh1, WH, kt, nt, lane);
            ldb(bl0, bl1, WL, kt, nt, lane);
            #pragma unroll
            for (int mt = 0; mt < 4; mt++) {
                mmabf(acc[mt][nt], aH[mt], bh0, bh1);
                mmabf(acc[mt][nt], aL[mt], bh0, bh1);
                mmabf(acc[mt][nt], aH[mt], bl0, bl1);
            }
        }
    }
    __syncwarp();
    epilogue_bf(acc, (float*)XH, lane, g_z2b + (size_t)bt*4096, g_psum2, g_psq2, bt);
}

// ---------------- K4: S = sum_t [relu(BN1(z1)) + relu(BN2(z2))]; edges ---------
__global__ void __launch_bounds__(256) k_sumfinal() {
    int bv = blockIdx.x, b = bv >> 6, v = bv & 63;
    int tid = threadIdx.x;
    int hq = (tid & 15) << 2, ph = tid >> 4;     // 16 h-quads x 16 t-phases
    float4 A1 = *(float4*)&g_a1[hq], C1 = *(float4*)&g_c1[hq];
    float4 A2 = *(float4*)&g_a2[hq], C2 = *(float4*)&g_c2[hq];
    float4 s = make_float4(0.f,0.f,0.f,0.f);
    float4 e0 = s, e1 = s;
    #pragma unroll 4
    for (int t = ph; t < TT; t += 16) {
        size_t i1 = (((size_t)(b*TT + t))*64 + v)*64 + hq;
        uint2 u1 = *(const uint2*)&g_z1b[i1];
        uint2 u2 = *(const uint2*)&g_z2b[i1];
        float x0 = fmaxf(fmaf(__uint_as_float(u1.x << 16),         A1.x, C1.x), 0.f)
                 + fmaxf(fmaf(__uint_as_float(u2.x << 16),         A2.x, C2.x), 0.f);
        float x1 = fmaxf(fmaf(__uint_as_float(u1.x & 0xffff0000u), A1.y, C1.y), 0.f)
                 + fmaxf(fmaf(__uint_as_float(u2.x & 0xffff0000u), A2.y, C2.y), 0.f);
        float x2 = fmaxf(fmaf(__uint_as_float(u1.y << 16),         A1.z, C1.z), 0.f)
                 + fmaxf(fmaf(__uint_as_float(u2.y << 16),         A2.z, C2.z), 0.f);
        float x3 = fmaxf(fmaf(__uint_as_float(u1.y & 0xffff0000u), A1.w, C1.w), 0.f)
                 + fmaxf(fmaf(__uint_as_float(u2.y & 0xffff0000u), A2.w, C2.w), 0.f);
        s.x += x0; s.y += x1; s.z += x2; s.w += x3;
        if (t == 0)    e0 = make_float4(x0, x1, x2, x3);
        if (t == TT-1) e1 = make_float4(x0, x1, x2, x3);
    }
    __shared__ float sr[16][64], se0[64], se1[64];
    *(float4*)&sr[ph][hq] = s;
    if (ph == 0)  *(float4*)&se0[hq] = e0;
    if (ph == 15) *(float4*)&se1[hq] = e1;
    __syncthreads();
    if (tid < 64) {
        float S = 0.f;
        #pragma unroll
        for (int p = 0; p < 16; p++) S += sr[p][tid];
        int o = b*4096 + v*64 + tid;
        g_S[o]  = S;
        g_E0[o] = se0[tid];
        g_E1[o] = se1[tid];
    }
}

// ---------------- K5: collapsed conv+mean --------------------------------------
__global__ void __launch_bounds__(256) k_pool(const float* __restrict__ tw,
                                              const float* __restrict__ tb) {
    int o = blockIdx.x, tid = threadIdx.x;
    float acc[BB];
    #pragma unroll
    for (int b = 0; b < BB; b++) acc[b] = 0.f;
    const float* two = tw + (size_t)o*VH*3;
    for (int i = tid; i < VH; i += 256) {
        float t0 = two[i*3+0], t1 = two[i*3+1], t2 = two[i*3+2];
        float ts = t0 + t1 + t2;
        #pragma unroll
        for (int b = 0; b < BB; b++) {
            int ix = b*VH + i;
            acc[b] += ts*g_S[ix] - t0*g_E1[ix] - t2*g_E0[ix];
        }
    }
    __shared__ float red[16][257];
    __shared__ float red2[16][17];
    #pragma unroll
    for (int b = 0; b < BB; b++) red[b][tid] = acc[b];
    __syncthreads();
    int g = tid >> 4, bq = tid & 15;
    float s = 0.f;
    #pragma unroll
    for (int k = 0; k < 16; k++) s += red[bq][g + k*16];
    red2[bq][g] = s;
    __syncthreads();
    if (tid < 16) {
        float tot = 0.f;
        #pragma unroll
        for (int k = 0; k < 16; k++) tot += red2[tid][k];
        g_y[tid*TC + o] = tot*(1.f/TT) + tb[o];
    }
}

// ---------------- K6: FC head ---------------------------------------------------
__global__ void __launch_bounds__(256) k_fc(const float* __restrict__ f1w,
                                            const float* __restrict__ f1b,
                                            const float* __restrict__ f2w,
                                            const float* __restrict__ f2b,
                                            float* __restrict__ out) {
    __shared__ float ys[BB*TC];
    __shared__ float hs[BB*128];
    int tid = threadIdx.x;
    for (int i = tid; i < BB*TC; i += 256) ys[i] = g_y[i];
    __syncthreads();
    int b = tid >> 4, jq = (tid & 15) * 8;
    float acc[8];
    #pragma unroll
    for (int j = 0; j < 8; j++) acc[j] = f1b[jq+j];
    for (int o = 0; o < TC; o++) {
        float yv = ys[b*TC + o];
        const float* w = f1w + o*128 + jq;
        #pragma unroll
        for (int j = 0; j < 8; j++) acc[j] += yv * w[j];
    }
    #pragma unroll
    for (int j = 0; j < 8; j++) hs[b*128 + jq + j] = fmaxf(acc[j], 0.f);
    __syncthreads();
    if (tid < BB*10) {
        int bb = tid / 10, n = tid % 10;
        float s = f2b[n];
        #pragma unroll 8
        for (int j = 0; j < 128; j++) s += hs[bb*128 + j] * f2w[j*10 + n];
        out[tid] = s;
    }
}

// ---------------- launch ---------------------------------------------------------
extern "C" void kernel_launch(void* const* d_in, const int* in_sizes, int n_in,
                              void* d_out, int out_size) {
    const float* x    = (const float*)d_in[0];
    const float* adj  = (const float*)d_in[1];
    const float* w1   = (const float*)d_in[2];
    const float* g1   = (const float*)d_in[4];
    const float* be1  = (const float*)d_in[5];
    const float* w2   = (const float*)d_in[6];
    const float* g2   = (const float*)d_in[8];
    const float* be2  = (const float*)d_in[9];
    const float* tw   = (const float*)d_in[10];
    const float* tb   = (const float*)d_in[11];
    const float* f1w  = (const float*)d_in[12];
    const float* f1b  = (const float*)d_in[13];
    const float* f2w  = (const float*)d_in[14];
    const float* f2b  = (const float*)d_in[15];
    float* out = (float*)d_out;

    cudaFuncSetAttribute(k_l1, cudaFuncAttributeMaxDynamicSharedMemorySize, L1_SM);
    cudaFuncSetAttribute(k_l2, cudaFuncAttributeMaxDynamicSharedMemorySize, L2_SM);

    k_prep<<<BB, 256>>>(adj, w1, w2);
    k_l1<<<BB*128, 128, L1_SM>>>(x);
    k_stats<<<HH, 256>>>(0, g1, be1);
    k_l2<<<BB*128, 128, L2_SM>>>();
    k_stats<<<HH, 256>>>(1, g2, be2);
    k_sumfinal<<<BB*VV, 256>>>();
    k_pool<<<TC, 256>>>(tw, tb);
    k_fc<<<1, 256>>>(f1w, f1b, f2w, f2b, out);
}

// round 10
// speedup vs baseline: 1.4735x; 1.0696x over previous
#include <cuda_runtime.h>
#include <cuda_bf16.h>
#include <cstdint>

#define BB 16
#define TT 512
#define VV 64
#define HH 64
#define BT (BB*TT)
#define VH (VV*HH)
#define TC 256

// ---------------- scratch ----------------------------------------------------
__device__ __nv_bfloat16 g_adjH[BB*4096], g_adjL[BB*4096]; // swizzled [b][v][w]
__device__ __nv_bfloat16 g_w1H[1024];                      // swizzled [c=16][h=64]
__device__ __nv_bfloat16 g_w2H[4096],  g_w2L[4096];        // swizzled [h][o]
__device__ __nv_bfloat16 g_z1b[(size_t)BT*VH];             // bf16 [bt][v][h]
__device__ __nv_bfloat16 g_z2b[(size_t)BT*VH];             // bf16 [bt][v][o]
__device__ float g_psum1[HH*BT], g_psq1[HH*BT];
__device__ float g_psum2[HH*BT], g_psq2[HH*BT];
__device__ float g_a1[HH], g_c1[HH], g_a2[HH], g_c2[HH];
__device__ float g_S[BB*VH], g_E0[BB*VH], g_E1[BB*VH];
__device__ float g_y[BB*TC];

extern __shared__ unsigned char s_dyn[];

// ---------------- helpers -----------------------------------------------------
__device__ __forceinline__ uint32_t toff(int r, int cB) {
    return (uint32_t)(r*128 + (cB ^ ((r & 7) << 4)));
}
__device__ __forceinline__ void ldsm4(uint32_t* r, unsigned char* p) {
    uint32_t a; asm("{ .reg .u64 t; cvta.to.shared.u64 t, %1; cvt.u32.u64 %0, t; }" : "=r"(a) : "l"(p));
    asm volatile("ldmatrix.sync.aligned.m8n8.x4.shared.b16 {%0,%1,%2,%3}, [%4];"
        : "=r"(r[0]), "=r"(r[1]), "=r"(r[2]), "=r"(r[3]) : "r"(a));
}
__device__ __forceinline__ void ldsm2t(uint32_t& r0, uint32_t& r1, unsigned char* p) {
    uint32_t a; asm("{ .reg .u64 t; cvta.to.shared.u64 t, %1; cvt.u32.u64 %0, t; }" : "=r"(a) : "l"(p));
    asm volatile("ldmatrix.sync.aligned.m8n8.x2.trans.shared.b16 {%0,%1}, [%2];"
        : "=r"(r0), "=r"(r1) : "r"(a));
}
__device__ __forceinline__ void mmabf(float* c, const uint32_t* a, uint32_t b0, uint32_t b1) {
    asm volatile("mma.sync.aligned.m16n8k16.row.col.f32.bf16.bf16.f32 "
        "{%0,%1,%2,%3},{%4,%5,%6,%7},{%8,%9},{%0,%1,%2,%3};"
        : "+f"(c[0]), "+f"(c[1]), "+f"(c[2]), "+f"(c[3])
        : "r"(a[0]), "r"(a[1]), "r"(a[2]), "r"(a[3]), "r"(b0), "r"(b1));
}
__device__ __forceinline__ uint32_t packbf(float f0, float f1) {
    uint32_t r;
    asm("cvt.rn.bf16x2.f32 %0, %1, %2;" : "=r"(r) : "f"(f1), "f"(f0));
    return r;
}
__device__ __forceinline__ void lda(uint32_t* a, unsigned char* base, int mt, int kt, int lane) {
    int row = mt*16 + (lane & 7) + (lane & 8);
    int cB  = kt*32 + ((lane >> 4) << 4);
    ldsm4(a, base + toff(row, cB));
}
__device__ __forceinline__ void ldb(uint32_t& b0, uint32_t& b1, unsigned char* base, int kt, int nt, int lane) {
    int row = kt*16 + (lane & 15);
    ldsm2t(b0, b1, base + toff(row, nt*16));
}

// ---------------- K0: prep ----------------------------------------------------
__global__ void k_prep(const float* __restrict__ adj, const float* __restrict__ w1,
                       const float* __restrict__ w2) {
    int b = blockIdx.x, tid = threadIdx.x;
    __shared__ float dis[64];
    const float* A = adj + b*4096;
    if (tid < 64) {
        float s = 0.f;
        #pragma unroll 8
        for (int w = 0; w < 64; w++) s += A[tid*64 + w];
        dis[tid] = rsqrtf(s + 1e-6f);
    }
    __syncthreads();
    for (int idx = tid; idx < 4096; idx += 256) {
        int v = idx >> 6, w = idx & 63;
        float a = dis[v] * A[idx] * dis[w];
        __nv_bfloat16 hb = __float2bfloat16(a);
        __nv_bfloat16 lb = __float2bfloat16(a - __bfloat162float(hb));
        uint32_t e = toff(v, w*2) >> 1;
        g_adjH[b*4096 + e] = hb; g_adjL[b*4096 + e] = lb;
    }
    if (b == 0) {
        for (int idx = tid; idx < 1024; idx += 256) {
            int c = idx >> 6, h = idx & 63;
            uint32_t e = toff(c, h*2) >> 1;
            g_w1H[e] = __float2bfloat16(w1[c*64 + h]);
        }
        for (int idx = tid; idx < 4096; idx += 256) {
            int h = idx >> 6, o = idx & 63;
            float val = w2[h*64 + o];
            __nv_bfloat16 hb = __float2bfloat16(val);
            __nv_bfloat16 lb = __float2bfloat16(val - __bfloat162float(hb));
            uint32_t e = toff(h, o*2) >> 1;
            g_w2H[e] = hb; g_w2L[e] = lb;
        }
    }
}

// ---------------- register epilogue: shuffle-stats + bf16 stage + store -------
__device__ __forceinline__ void epilogue_reg(float acc[4][8][4], unsigned char* stage, int lane,
                                             __nv_bfloat16* zout, float* psum, float* psq, int bt) {
    // BN partials per column via shuffle (fixed order -> deterministic)
    #pragma unroll
    for (int nt = 0; nt < 8; nt++) {
        float p0=0.f, p1=0.f, r0=0.f, r1=0.f;
        #pragma unroll
        for (int mt = 0; mt < 4; mt++) {
            float a0=acc[mt][nt][0], a1=acc[mt][nt][1], a2=acc[mt][nt][2], a3=acc[mt][nt][3];
            p0 += a0 + a2; p1 += a1 + a3;
            r0 += a0*a0 + a2*a2; r1 += a1*a1 + a3*a3;
        }
        #pragma unroll
        for (int d = 4; d < 32; d <<= 1) {
            p0 += __shfl_xor_sync(0xffffffffu, p0, d);
            p1 += __shfl_xor_sync(0xffffffffu, p1, d);
            r0 += __shfl_xor_sync(0xffffffffu, r0, d);
            r1 += __shfl_xor_sync(0xffffffffu, r1, d);
        }
        if (lane < 4) {
            int c = nt*8 + lane*2;
            psum[c*BT + bt] = p0; psum[(c+1)*BT + bt] = p1;
            psq[c*BT + bt]  = r0; psq[(c+1)*BT + bt]  = r1;
        }
    }
    // stage bf16 tile (swizzled), then coalesced 16B stores
    #pragma unroll
    for (int mt = 0; mt < 4; mt++)
        #pragma unroll
        for (int nt = 0; nt < 8; nt++) {
            int r = mt*16 + (lane >> 2), cB = (nt*8 + (lane & 3)*2)*2;
            *(uint32_t*)(stage + toff(r, cB))   = packbf(acc[mt][nt][0], acc[mt][nt][1]);
            *(uint32_t*)(stage + toff(r+8, cB)) = packbf(acc[mt][nt][2], acc[mt][nt][3]);
        }
    __syncwarp();
    #pragma unroll
    for (int it = 0; it < 16; it++) {
        int idx = it*32 + lane;
        int r = idx >> 3, cB = (idx & 7) * 16;
        uint4 v = *(uint4*)(stage + toff(r, cB));
        *(uint4*)((unsigned char*)zout + r*128 + cB) = v;
    }
}

// ---------------- K1: layer1 HMMA ----------------------------------------------
// smem: AH 0(8K) AL 8K(8K) W1H 16384(2K) | wreg 18432 + wq*8192
#define L1_WREG 18432
#define L1_SM   (18432 + 4*8192)
__global__ void __launch_bounds__(128, 3) k_l1(const float* __restrict__ x) {
    int blk = blockIdx.x, b = blk >> 7, chunk = blk & 127;
    int tid = threadIdx.x, lane = tid & 31, wq = tid >> 5;
    unsigned char* sm = s_dyn;
    {
        const uint4* s1 = (const uint4*)(g_adjH + b*4096);
        const uint4* s2 = (const uint4*)(g_adjL + b*4096);
        uint4* d1 = (uint4*)sm; uint4* d2 = (uint4*)(sm + 8192);
        for (int i = tid; i < 512; i += 128) { d1[i] = s1[i]; d2[i] = s2[i]; }
        const uint4* s3 = (const uint4*)g_w1H;
        uint4* d3 = (uint4*)(sm + 16384);
        if (tid < 128) d3[tid] = s3[tid];
    }
    __syncthreads();

    int t = chunk*4 + wq;
    int bt = b*TT + t;
    unsigned char* XH = sm + L1_WREG + wq*8192;
    unsigned char* AH = sm; unsigned char* AL = sm + 8192;
    unsigned char* WH = sm + 16384;

    // build X tile [w=64][c=16] bf16 hi
    const float* xg = x + (size_t)bt*1024;
    #pragma unroll
    for (int it = 0; it < 8; it++) {
        int idx = it*32 + lane;
        int r = idx >> 2, cq = (idx & 3) << 2;
        float4 u = *(const float4*)&xg[r*16 + cq];
        *(uint2*)(XH + toff(r, cq*2)) = make_uint2(packbf(u.x, u.y), packbf(u.z, u.w));
    }
    __syncwarp();

    // GEMM1': tmp[v][c] = sum_w A[v][w] X[w][c]  (A hi/lo)
    float acc1[4][2][4];
    #pragma unroll
    for (int m = 0; m < 4; m++)
        #pragma unroll
        for (int n = 0; n < 2; n++) { acc1[m][n][0]=0; acc1[m][n][1]=0; acc1[m][n][2]=0; acc1[m][n][3]=0; }
    #pragma unroll
    for (int kt = 0; kt < 4; kt++) {
        uint32_t aH[4][4], aL[4][4];
        #pragma unroll
        for (int mt = 0; mt < 4; mt++) { lda(aH[mt], AH, mt, kt, lane); lda(aL[mt], AL, mt, kt, lane); }
        #pragma unroll
        for (int nt = 0; nt < 2; nt++) {
            uint32_t bh0, bh1;
            ldb(bh0, bh1, XH, kt, nt, lane);
            #pragma unroll
            for (int mt = 0; mt < 4; mt++) {
                mmabf(acc1[mt][nt], aH[mt], bh0, bh1);
                mmabf(acc1[mt][nt], aL[mt], bh0, bh1);
            }
        }
    }
    __syncwarp();
    // store tmp hi (bf16) over X region
    #pragma unroll
    for (int mt = 0; mt < 4; mt++)
        #pragma unroll
        for (int nt = 0; nt < 2; nt++) {
            int r = mt*16 + (lane >> 2), cB = (nt*8 + (lane & 3)*2)*2;
            *(uint32_t*)(XH + toff(r, cB))   = packbf(acc1[mt][nt][0], acc1[mt][nt][1]);
            *(uint32_t*)(XH + toff(r+8, cB)) = packbf(acc1[mt][nt][2], acc1[mt][nt][3]);
        }
    __syncwarp();

    // GEMM2': z1[v][h] = sum_c tmp[v][c] W1[c][h]  (1-term)
    float acc2[4][8][4];
    #pragma unroll
    for (int m = 0; m < 4; m++)
        #pragma unroll
        for (int n = 0; n < 8; n++) { acc2[m][n][0]=0; acc2[m][n][1]=0; acc2[m][n][2]=0; acc2[m][n][3]=0; }
    {
        uint32_t aH[4][4];
        #pragma unroll
        for (int mt = 0; mt < 4; mt++) lda(aH[mt], XH, mt, 0, lane);
        #pragma unroll
        for (int nt = 0; nt < 8; nt++) {
            uint32_t bh0, bh1;
            ldb(bh0, bh1, WH, 0, nt, lane);
            #pragma unroll
            for (int mt = 0; mt < 4; mt++) mmabf(acc2[mt][nt], aH[mt], bh0, bh1);
        }
    }
    __syncwarp();
    epilogue_reg(acc2, XH, lane, g_z1b + (size_t)bt*4096, g_psum1, g_psq1, bt);
}

// ---------------- K2: finalize BN affine ---------------------------------------
__global__ void k_stats(int layer, const float* __restrict__ g, const float* __restrict__ be) {
    int h = blockIdx.x, tid = threadIdx.x;
    const float* ps = layer ? g_psum2 : g_psum1;
    const float* pq = layer ? g_psq2  : g_psq1;
    __shared__ float ss[256], sq[256];
    float s = 0.f, q = 0.f;
    for (int i = tid; i < BT; i += 256) { s += ps[h*BT + i]; q += pq[h*BT + i]; }
    ss[tid] = s; sq[tid] = q;
    __syncthreads();
    for (int st = 128; st > 0; st >>= 1) {
        if (tid < st) { ss[tid] += ss[tid+st]; sq[tid] += sq[tid+st]; }
        __syncthreads();
    }
    if (tid == 0) {
        const float N = (float)(BT*VV);
        float mean = ss[0] / N;
        float var  = sq[0] / N - mean*mean;
        float av = g[h] * rsqrtf(var + 1e-5f);
        if (layer) { g_a2[h] = av; g_c2[h] = be[h] - mean*av; }
        else       { g_a1[h] = av; g_c1[h] = be[h] - mean*av; }
    }
}

// ---------------- K3: layer2 HMMA ----------------------------------------------
// smem: AH 0(8K) W2H 8192(8K) W2L 16384(8K) a1/c1 24576(512B) | wreg 25088 + wq*8192
#define L2_WREG 25088
#define L2_SM   (25088 + 4*8192)
__global__ void __launch_bounds__(128, 3) k_l2() {
    int blk = blockIdx.x, b = blk >> 7, chunk = blk & 127;
    int tid = threadIdx.x, lane = tid & 31, wq = tid >> 5;
    unsigned char* sm = s_dyn;
    float* a1s = (float*)(sm + 24576);
    float* c1s = a1s + 64;
    {
        const uint4* s1 = (const uint4*)(g_adjH + b*4096);
        uint4* d1 = (uint4*)sm;
        for (int i = tid; i < 512; i += 128) d1[i] = s1[i];
        const uint4* s3 = (const uint4*)g_w2H; const uint4* s4 = (const uint4*)g_w2L;
        uint4* d3 = (uint4*)(sm + 8192); uint4* d4 = (uint4*)(sm + 16384);
        for (int i = tid; i < 512; i += 128) { d3[i] = s3[i]; d4[i] = s4[i]; }
        if (tid < 64) { a1s[tid] = g_a1[tid]; c1s[tid] = g_c1[tid]; }
    }
    __syncthreads();

    int t = chunk*4 + wq;
    int bt = b*TT + t;
    unsigned char* XH = sm + L2_WREG + wq*8192;
    unsigned char* AH = sm;
    unsigned char* WH = sm + 8192; unsigned char* WL = sm + 16384;

    // build x1 tile [w=64][h=64] = relu(a1*z1+c1) from bf16 z1, hi only
    const unsigned char* ztb = (const unsigned char*)(g_z1b + (size_t)bt*4096);
    #pragma unroll
    for (int it = 0; it < 32; it++) {
        int idx = it*32 + lane;
        int r = idx >> 4, cq = (idx & 15) << 2;
        uint2 u = *(const uint2*)(ztb + (r*64 + cq)*2);
        float4 av = *(float4*)&a1s[cq];
        float4 cv = *(float4*)&c1s[cq];
        float e0 = fmaxf(fmaf(__uint_as_float(u.x << 16),         av.x, cv.x), 0.f);
        float e1 = fmaxf(fmaf(__uint_as_float(u.x & 0xffff0000u), av.y, cv.y), 0.f);
        float e2 = fmaxf(fmaf(__uint_as_float(u.y << 16),         av.z, cv.z), 0.f);
        float e3 = fmaxf(fmaf(__uint_as_float(u.y & 0xffff0000u), av.w, cv.w), 0.f);
        *(uint2*)(XH + toff(r, cq*2)) = make_uint2(packbf(e0, e1), packbf(e2, e3));
    }
    __syncwarp();

    float acc[4][8][4];
    #pragma unroll
    for (int m = 0; m < 4; m++)
        #pragma unroll
        for (int n = 0; n < 8; n++) { acc[m][n][0]=0; acc[m][n][1]=0; acc[m][n][2]=0; acc[m][n][3]=0; }

    // GEMM1: tmp[v][h] = sum_w A[v][w] x1[w][h]  (1-term)
    #pragma unroll
    for (int kt = 0; kt < 4; kt++) {
        uint32_t aH[4][4];
        #pragma unroll
        for (int mt = 0; mt < 4; mt++) lda(aH[mt], AH, mt, kt, lane);
        #pragma unroll
        for (int nt = 0; nt < 8; nt++) {
            uint32_t bh0, bh1;
            ldb(bh0, bh1, XH, kt, nt, lane);
            #pragma unroll
            for (int mt = 0; mt < 4; mt++) mmabf(acc[mt][nt], aH[mt], bh0, bh1);
        }
    }
    __syncwarp();
    // store tmp hi (bf16) over x1 region
    #pragma unroll
    for (int mt = 0; mt < 4; mt++)
        #pragma unroll
        for (int nt = 0; nt < 8; nt++) {
            int r = mt*16 + (lane >> 2), cB = (nt*8 + (lane & 3)*2)*2;
            *(uint32_t*)(XH + toff(r, cB))   = packbf(acc[mt][nt][0], acc[mt][nt][1]);
            *(uint32_t*)(XH + toff(r+8, cB)) = packbf(acc[mt][nt][2], acc[mt][nt][3]);
        }
    __syncwarp();

    // GEMM2: z2[v][o] = sum_h tmp[v][h] W2[h][o]  (2-term: tmpH x W2 hi/lo)
    #pragma unroll
    for (int m = 0; m < 4; m++)
        #pragma unroll
        for (int n = 0; n < 8; n++) { acc[m][n][0]=0; acc[m][n][1]=0; acc[m][n][2]=0; acc[m][n][3]=0; }
    #pragma unroll
    for (int kt = 0; kt < 4; kt++) {
        uint32_t aH[4][4];
        #pragma unroll
        for (int mt = 0; mt < 4; mt++) lda(aH[mt], XH, mt, kt, lane);
        #pragma unroll
        for (int nt = 0; nt < 8; nt++) {
            uint32_t bh0, bh1, bl0, bl1;
            ldb(bh0, bh1, WH, kt, nt, lane);
            ldb(bl0, bl1, WL, kt, nt, lane);
            #pragma unroll
            for (int mt = 0; mt < 4; mt++) {
                mmabf(acc[mt][nt], aH[mt], bh0, bh1);
                mmabf(acc[mt][nt], aH[mt], bl0, bl1);
            }
        }
    }
    __syncwarp();
    epilogue_reg(acc, XH, lane, g_z2b + (size_t)bt*4096, g_psum2, g_psq2, bt);
}

// ---------------- K4: S = sum_t [relu(BN1(z1)) + relu(BN2(z2))]; edges ---------
__global__ void __launch_bounds__(256) k_sumfinal() {
    int bv = blockIdx.x, b = bv >> 6, v = bv & 63;
    int tid = threadIdx.x;
    int hq = (tid & 15) << 2, ph = tid >> 4;     // 16 h-quads x 16 t-phases
    float4 A1 = *(float4*)&g_a1[hq], C1 = *(float4*)&g_c1[hq];
    float4 A2 = *(float4*)&g_a2[hq], C2 = *(float4*)&g_c2[hq];
    float4 s = make_float4(0.f,0.f,0.f,0.f);
    float4 e0 = s, e1 = s;
    #pragma unroll 4
    for (int t = ph; t < TT; t += 16) {
        size_t i1 = (((size_t)(b*TT + t))*64 + v)*64 + hq;
        uint2 u1 = *(const uint2*)&g_z1b[i1];
        uint2 u2 = *(const uint2*)&g_z2b[i1];
        float x0 = fmaxf(fmaf(__uint_as_float(u1.x << 16),         A1.x, C1.x), 0.f)
                 + fmaxf(fmaf(__uint_as_float(u2.x << 16),         A2.x, C2.x), 0.f);
        float x1 = fmaxf(fmaf(__uint_as_float(u1.x & 0xffff0000u), A1.y, C1.y), 0.f)
                 + fmaxf(fmaf(__uint_as_float(u2.x & 0xffff0000u), A2.y, C2.y), 0.f);
        float x2 = fmaxf(fmaf(__uint_as_float(u1.y << 16),         A1.z, C1.z), 0.f)
                 + fmaxf(fmaf(__uint_as_float(u2.y << 16),         A2.z, C2.z), 0.f);
        float x3 = fmaxf(fmaf(__uint_as_float(u1.y & 0xffff0000u), A1.w, C1.w), 0.f)
                 + fmaxf(fmaf(__uint_as_float(u2.y & 0xffff0000u), A2.w, C2.w), 0.f);
        s.x += x0; s.y += x1; s.z += x2; s.w += x3;
        if (t == 0)    e0 = make_float4(x0, x1, x2, x3);
        if (t == TT-1) e1 = make_float4(x0, x1, x2, x3);
    }
    __shared__ float sr[16][64], se0[64], se1[64];
    *(float4*)&sr[ph][hq] = s;
    if (ph == 0)  *(float4*)&se0[hq] = e0;
    if (ph == 15) *(float4*)&se1[hq] = e1;
    __syncthreads();
    if (tid < 64) {
        float S = 0.f;
        #pragma unroll
        for (int p = 0; p < 16; p++) S += sr[p][tid];
        int o = b*4096 + v*64 + tid;
        g_S[o]  = S;
        g_E0[o] = se0[tid];
        g_E1[o] = se1[tid];
    }
}

// ---------------- K5: collapsed conv+mean --------------------------------------
__global__ void __launch_bounds__(256) k_pool(const float* __restrict__ tw,
                                              const float* __restrict__ tb) {
    int o = blockIdx.x, tid = threadIdx.x;
    float acc[BB];
    #pragma unroll
    for (int b = 0; b < BB; b++) acc[b] = 0.f;
    const float* two = tw + (size_t)o*VH*3;
    for (int i = tid; i < VH; i += 256) {
        float t0 = two[i*3+0], t1 = two[i*3+1], t2 = two[i*3+2];
        float ts = t0 + t1 + t2;
        #pragma unroll
        for (int b = 0; b < BB; b++) {
            int ix = b*VH + i;
            acc[b] += ts*g_S[ix] - t0*g_E1[ix] - t2*g_E0[ix];
        }
    }
    __shared__ float red[16][257];
    __shared__ float red2[16][17];
    #pragma unroll
    for (int b = 0; b < BB; b++) red[b][tid] = acc[b];
    __syncthreads();
    int g = tid >> 4, bq = tid & 15;
    float s = 0.f;
    #pragma unroll
    for (int k = 0; k < 16; k++) s += red[bq][g + k*16];
    red2[bq][g] = s;
    __syncthreads();
    if (tid < 16) {
        float tot = 0.f;
        #pragma unroll
        for (int k = 0; k < 16; k++) tot += red2[tid][k];
        g_y[tid*TC + o] = tot*(1.f/TT) + tb[o];
    }
}

// ---------------- K6: FC head ---------------------------------------------------
__global__ void __launch_bounds__(256) k_fc(const float* __restrict__ f1w,
                                            const float* __restrict__ f1b,
                                            const float* __restrict__ f2w,
                                            const float* __restrict__ f2b,
                                            float* __restrict__ out) {
    __shared__ float ys[BB*TC];
    __shared__ float hs[BB*128];
    int tid = threadIdx.x;
    for (int i = tid; i < BB*TC; i += 256) ys[i] = g_y[i];
    __syncthreads();
    int b = tid >> 4, jq = (tid & 15) * 8;
    float acc[8];
    #pragma unroll
    for (int j = 0; j < 8; j++) acc[j] = f1b[jq+j];
    for (int o = 0; o < TC; o++) {
        float yv = ys[b*TC + o];
        const float* w = f1w + o*128 + jq;
        #pragma unroll
        for (int j = 0; j < 8; j++) acc[j] += yv * w[j];
    }
    #pragma unroll
    for (int j = 0; j < 8; j++) hs[b*128 + jq + j] = fmaxf(acc[j], 0.f);
    __syncthreads();
    if (tid < BB*10) {
        int bb = tid / 10, n = tid % 10;
        float s = f2b[n];
        #pragma unroll 8
        for (int j = 0; j < 128; j++) s += hs[bb*128 + j] * f2w[j*10 + n];
        out[tid] = s;
    }
}

// ---------------- launch ---------------------------------------------------------
extern "C" void kernel_launch(void* const* d_in, const int* in_sizes, int n_in,
                              void* d_out, int out_size) {
    const float* x    = (const float*)d_in[0];
    const float* adj  = (const float*)d_in[1];
    const float* w1   = (const float*)d_in[2];
    const float* g1   = (const float*)d_in[4];
    const float* be1  = (const float*)d_in[5];
    const float* w2   = (const float*)d_in[6];
    const float* g2   = (const float*)d_in[8];
    const float* be2  = (const float*)d_in[9];
    const float* tw   = (const float*)d_in[10];
    const float* tb   = (const float*)d_in[11];
    const float* f1w  = (const float*)d_in[12];
    const float* f1b  = (const float*)d_in[13];
    const float* f2w  = (const float*)d_in[14];
    const float* f2b  = (const float*)d_in[15];
    float* out = (float*)d_out;

    cudaFuncSetAttribute(k_l1, cudaFuncAttributeMaxDynamicSharedMemorySize, L1_SM);
    cudaFuncSetAttribute(k_l2, cudaFuncAttributeMaxDynamicSharedMemorySize, L2_SM);

    k_prep<<<BB, 256>>>(adj, w1, w2);
    k_l1<<<BB*128, 128, L1_SM>>>(x);
    k_stats<<<HH, 256>>>(0, g1, be1);
    k_l2<<<BB*128, 128, L2_SM>>>();
    k_stats<<<HH, 256>>>(1, g2, be2);
    k_sumfinal<<<BB*VV, 256>>>();
    k_pool<<<TC, 256>>>(tw, tb);
    k_fc<<<1, 256>>>(f1w, f1b, f2w, f2b, out);
}

// round 11
// speedup vs baseline: 1.5210x; 1.0323x over previous
#include <cuda_runtime.h>
#include <cuda_bf16.h>
#include <cstdint>

#define BB 16
#define TT 512
#define VV 64
#define HH 64
#define BT (BB*TT)
#define VH (VV*HH)
#define TC 256

// ---------------- scratch ----------------------------------------------------
__device__ __nv_bfloat16 g_adjH[BB*4096], g_adjL[BB*4096]; // swizzled [b][v][w]
__device__ __nv_bfloat16 g_w1H[1024];                      // swizzled [c=16][h=64]
__device__ __nv_bfloat16 g_w2H[4096];                      // swizzled [h][o]
__device__ __nv_bfloat16 g_z1b[(size_t)BT*VH];             // bf16 [bt][v][h]
__device__ __nv_bfloat16 g_z2b[(size_t)BT*VH];             // bf16 [bt][v][o]
__device__ float g_psum1[HH*BT], g_psq1[HH*BT];
__device__ float g_psum2[HH*BT], g_psq2[HH*BT];
__device__ float g_a1[HH], g_c1[HH], g_a2[HH], g_c2[HH];
__device__ float g_S[BB*VH], g_E0[BB*VH], g_E1[BB*VH];
__device__ float g_y[BB*TC];

extern __shared__ unsigned char s_dyn[];

// ---------------- helpers -----------------------------------------------------
__device__ __forceinline__ uint32_t toff(int r, int cB) {
    return (uint32_t)(r*128 + (cB ^ ((r & 7) << 4)));
}
__device__ __forceinline__ void ldsm4(uint32_t* r, unsigned char* p) {
    uint32_t a; asm("{ .reg .u64 t; cvta.to.shared.u64 t, %1; cvt.u32.u64 %0, t; }" : "=r"(a) : "l"(p));
    asm volatile("ldmatrix.sync.aligned.m8n8.x4.shared.b16 {%0,%1,%2,%3}, [%4];"
        : "=r"(r[0]), "=r"(r[1]), "=r"(r[2]), "=r"(r[3]) : "r"(a));
}
__device__ __forceinline__ void ldsm4t(uint32_t* r, unsigned char* p) {
    uint32_t a; asm("{ .reg .u64 t; cvta.to.shared.u64 t, %1; cvt.u32.u64 %0, t; }" : "=r"(a) : "l"(p));
    asm volatile("ldmatrix.sync.aligned.m8n8.x4.trans.shared.b16 {%0,%1,%2,%3}, [%4];"
        : "=r"(r[0]), "=r"(r[1]), "=r"(r[2]), "=r"(r[3]) : "r"(a));
}
__device__ __forceinline__ void mmabf(float* c, const uint32_t* a, uint32_t b0, uint32_t b1) {
    asm volatile("mma.sync.aligned.m16n8k16.row.col.f32.bf16.bf16.f32 "
        "{%0,%1,%2,%3},{%4,%5,%6,%7},{%8,%9},{%0,%1,%2,%3};"
        : "+f"(c[0]), "+f"(c[1]), "+f"(c[2]), "+f"(c[3])
        : "r"(a[0]), "r"(a[1]), "r"(a[2]), "r"(a[3]), "r"(b0), "r"(b1));
}
__device__ __forceinline__ uint32_t packbf(float f0, float f1) {
    uint32_t r;
    asm("cvt.rn.bf16x2.f32 %0, %1, %2;" : "=r"(r) : "f"(f1), "f"(f0));
    return r;
}
// A fragment (16x16 at mt,kt)
__device__ __forceinline__ void lda(uint32_t* a, unsigned char* base, int mt, int kt, int lane) {
    int row = mt*16 + (lane & 7) + (lane & 8);
    int cB  = kt*32 + ((lane >> 4) << 4);
    ldsm4(a, base + toff(row, cB));
}
// B fragments for TWO adjacent n-tiles (16x16 block at kt, ntp) via x4 trans:
// bq[0..1] -> nt = 2*ntp, bq[2..3] -> nt = 2*ntp+1
__device__ __forceinline__ void ldb4(uint32_t* bq, unsigned char* base, int kt, int ntp, int lane) {
    int g = lane >> 3;
    int row = kt*16 + ((g & 1) << 3) + (lane & 7);
    int cB  = ntp*32 + ((g >> 1) << 4);
    ldsm4t(bq, base + toff(row, cB));
}

// ---------------- K0: prep ----------------------------------------------------
__global__ void k_prep(const float* __restrict__ adj, const float* __restrict__ w1,
                       const float* __restrict__ w2) {
    int b = blockIdx.x, tid = threadIdx.x;
    __shared__ float dis[64];
    const float* A = adj + b*4096;
    if (tid < 64) {
        float s = 0.f;
        #pragma unroll 8
        for (int w = 0; w < 64; w++) s += A[tid*64 + w];
        dis[tid] = rsqrtf(s + 1e-6f);
    }
    __syncthreads();
    for (int idx = tid; idx < 4096; idx += 256) {
        int v = idx >> 6, w = idx & 63;
        float a = dis[v] * A[idx] * dis[w];
        __nv_bfloat16 hb = __float2bfloat16(a);
        __nv_bfloat16 lb = __float2bfloat16(a - __bfloat162float(hb));
        uint32_t e = toff(v, w*2) >> 1;
        g_adjH[b*4096 + e] = hb; g_adjL[b*4096 + e] = lb;
    }
    if (b == 0) {
        for (int idx = tid; idx < 1024; idx += 256) {
            int c = idx >> 6, h = idx & 63;
            uint32_t e = toff(c, h*2) >> 1;
            g_w1H[e] = __float2bfloat16(w1[c*64 + h]);
        }
        for (int idx = tid; idx < 4096; idx += 256) {
            int h = idx >> 6, o = idx & 63;
            uint32_t e = toff(h, o*2) >> 1;
            g_w2H[e] = __float2bfloat16(w2[h*64 + o]);
        }
    }
}

// ---------------- register epilogue: shuffle-stats + bf16 stage + store -------
__device__ __forceinline__ void epilogue_reg(float acc[4][8][4], unsigned char* stage, int lane,
                                             __nv_bfloat16* zout, float* psum, float* psq, int bt) {
    #pragma unroll
    for (int nt = 0; nt < 8; nt++) {
        float p0=0.f, p1=0.f, r0=0.f, r1=0.f;
        #pragma unroll
        for (int mt = 0; mt < 4; mt++) {
            float a0=acc[mt][nt][0], a1=acc[mt][nt][1], a2=acc[mt][nt][2], a3=acc[mt][nt][3];
            p0 += a0 + a2; p1 += a1 + a3;
            r0 += a0*a0 + a2*a2; r1 += a1*a1 + a3*a3;
        }
        #pragma unroll
        for (int d = 4; d < 32; d <<= 1) {
            p0 += __shfl_xor_sync(0xffffffffu, p0, d);
            p1 += __shfl_xor_sync(0xffffffffu, p1, d);
            r0 += __shfl_xor_sync(0xffffffffu, r0, d);
            r1 += __shfl_xor_sync(0xffffffffu, r1, d);
        }
        if (lane < 4) {
            int c = nt*8 + lane*2;
            psum[c*BT + bt] = p0; psum[(c+1)*BT + bt] = p1;
            psq[c*BT + bt]  = r0; psq[(c+1)*BT + bt]  = r1;
        }
    }
    #pragma unroll
    for (int mt = 0; mt < 4; mt++)
        #pragma unroll
        for (int nt = 0; nt < 8; nt++) {
            int r = mt*16 + (lane >> 2), cB = (nt*8 + (lane & 3)*2)*2;
            *(uint32_t*)(stage + toff(r, cB))   = packbf(acc[mt][nt][0], acc[mt][nt][1]);
            *(uint32_t*)(stage + toff(r+8, cB)) = packbf(acc[mt][nt][2], acc[mt][nt][3]);
        }
    __syncwarp();
    #pragma unroll
    for (int it = 0; it < 16; it++) {
        int idx = it*32 + lane;
        int r = idx >> 3, cB = (idx & 7) * 16;
        uint4 v = *(uint4*)(stage + toff(r, cB));
        *(uint4*)((unsigned char*)zout + r*128 + cB) = v;
    }
}

// ---------------- K1: layer1 HMMA ----------------------------------------------
// smem: AH 0(8K) AL 8192(8K) W1H 16384(2K) | wreg 18432 + wq*8192
#define L1_WREG 18432
#define L1_SM   (18432 + 4*8192)
__global__ void __launch_bounds__(128, 3) k_l1(const float* __restrict__ x) {
    int blk = blockIdx.x, b = blk >> 7, chunk = blk & 127;
    int tid = threadIdx.x, lane = tid & 31, wq = tid >> 5;
    unsigned char* sm = s_dyn;
    {
        const uint4* s1 = (const uint4*)(g_adjH + b*4096);
        const uint4* s2 = (const uint4*)(g_adjL + b*4096);
        uint4* d1 = (uint4*)sm; uint4* d2 = (uint4*)(sm + 8192);
        for (int i = tid; i < 512; i += 128) { d1[i] = s1[i]; d2[i] = s2[i]; }
        const uint4* s3 = (const uint4*)g_w1H;
        uint4* d3 = (uint4*)(sm + 16384);
        if (tid < 128) d3[tid] = s3[tid];
    }
    __syncthreads();

    int t = chunk*4 + wq;
    int bt = b*TT + t;
    unsigned char* XH = sm + L1_WREG + wq*8192;
    unsigned char* AH = sm; unsigned char* AL = sm + 8192;
    unsigned char* WH = sm + 16384;

    // build X tile [w=64][c=16] bf16 hi
    const float* xg = x + (size_t)bt*1024;
    #pragma unroll
    for (int it = 0; it < 8; it++) {
        int idx = it*32 + lane;
        int r = idx >> 2, cq = (idx & 3) << 2;
        float4 u = *(const float4*)&xg[r*16 + cq];
        *(uint2*)(XH + toff(r, cq*2)) = make_uint2(packbf(u.x, u.y), packbf(u.z, u.w));
    }
    __syncwarp();

    // GEMM1': tmp[v][c] = sum_w A[v][w] X[w][c]  (A hi/lo)
    float acc1[4][2][4];
    #pragma unroll
    for (int m = 0; m < 4; m++)
        #pragma unroll
        for (int n = 0; n < 2; n++) { acc1[m][n][0]=0; acc1[m][n][1]=0; acc1[m][n][2]=0; acc1[m][n][3]=0; }
    #pragma unroll
    for (int kt = 0; kt < 4; kt++) {
        uint32_t aH[4][4], aL[4][4], bq[4];
        #pragma unroll
        for (int mt = 0; mt < 4; mt++) { lda(aH[mt], AH, mt, kt, lane); lda(aL[mt], AL, mt, kt, lane); }
        ldb4(bq, XH, kt, 0, lane);
        #pragma unroll
        for (int mt = 0; mt < 4; mt++) {
            mmabf(acc1[mt][0], aH[mt], bq[0], bq[1]);
            mmabf(acc1[mt][0], aL[mt], bq[0], bq[1]);
            mmabf(acc1[mt][1], aH[mt], bq[2], bq[3]);
            mmabf(acc1[mt][1], aL[mt], bq[2], bq[3]);
        }
    }
    __syncwarp();
    // store tmp hi (bf16) over X region
    #pragma unroll
    for (int mt = 0; mt < 4; mt++)
        #pragma unroll
        for (int nt = 0; nt < 2; nt++) {
            int r = mt*16 + (lane >> 2), cB = (nt*8 + (lane & 3)*2)*2;
            *(uint32_t*)(XH + toff(r, cB))   = packbf(acc1[mt][nt][0], acc1[mt][nt][1]);
            *(uint32_t*)(XH + toff(r+8, cB)) = packbf(acc1[mt][nt][2], acc1[mt][nt][3]);
        }
    __syncwarp();

    // GEMM2': z1[v][h] = sum_c tmp[v][c] W1[c][h]  (1-term)
    float acc2[4][8][4];
    #pragma unroll
    for (int m = 0; m < 4; m++)
        #pragma unroll
        for (int n = 0; n < 8; n++) { acc2[m][n][0]=0; acc2[m][n][1]=0; acc2[m][n][2]=0; acc2[m][n][3]=0; }
    {
        uint32_t aH[4][4];
        #pragma unroll
        for (int mt = 0; mt < 4; mt++) lda(aH[mt], XH, mt, 0, lane);
        #pragma unroll
        for (int ntp = 0; ntp < 4; ntp++) {
            uint32_t bq[4];
            ldb4(bq, WH, 0, ntp, lane);
            #pragma unroll
            for (int mt = 0; mt < 4; mt++) {
                mmabf(acc2[mt][2*ntp],   aH[mt], bq[0], bq[1]);
                mmabf(acc2[mt][2*ntp+1], aH[mt], bq[2], bq[3]);
            }
        }
    }
    __syncwarp();
    epilogue_reg(acc2, XH, lane, g_z1b + (size_t)bt*4096, g_psum1, g_psq1, bt);
}

// ---------------- K2: finalize BN affine ---------------------------------------
__global__ void k_stats(int layer, const float* __restrict__ g, const float* __restrict__ be) {
    int h = blockIdx.x, tid = threadIdx.x;
    const float* ps = layer ? g_psum2 : g_psum1;
    const float* pq = layer ? g_psq2  : g_psq1;
    __shared__ float ss[256], sq[256];
    float s = 0.f, q = 0.f;
    for (int i = tid; i < BT; i += 256) { s += ps[h*BT + i]; q += pq[h*BT + i]; }
    ss[tid] = s; sq[tid] = q;
    __syncthreads();
    for (int st = 128; st > 0; st >>= 1) {
        if (tid < st) { ss[tid] += ss[tid+st]; sq[tid] += sq[tid+st]; }
        __syncthreads();
    }
    if (tid == 0) {
        const float N = (float)(BT*VV);
        float mean = ss[0] / N;
        float var  = sq[0] / N - mean*mean;
        float av = g[h] * rsqrtf(var + 1e-5f);
        if (layer) { g_a2[h] = av; g_c2[h] = be[h] - mean*av; }
        else       { g_a1[h] = av; g_c1[h] = be[h] - mean*av; }
    }
}

// ---------------- K3: layer2 HMMA ----------------------------------------------
// smem: AH 0(8K) W2H 8192(8K) a1/c1 16384(512B) | wreg 16896 + wq*8192
#define L2_WREG 16896
#define L2_SM   (16896 + 4*8192)
__global__ void __launch_bounds__(128, 3) k_l2() {
    int blk = blockIdx.x, b = blk >> 7, chunk = blk & 127;
    int tid = threadIdx.x, lane = tid & 31, wq = tid >> 5;
    unsigned char* sm = s_dyn;
    float* a1s = (float*)(sm + 16384);
    float* c1s = a1s + 64;
    {
        const uint4* s1 = (const uint4*)(g_adjH + b*4096);
        uint4* d1 = (uint4*)sm;
        for (int i = tid; i < 512; i += 128) d1[i] = s1[i];
        const uint4* s3 = (const uint4*)g_w2H;
        uint4* d3 = (uint4*)(sm + 8192);
        for (int i = tid; i < 512; i += 128) d3[i] = s3[i];
        if (tid < 64) { a1s[tid] = g_a1[tid]; c1s[tid] = g_c1[tid]; }
    }
    __syncthreads();

    int t = chunk*4 + wq;
    int bt = b*TT + t;
    unsigned char* XH = sm + L2_WREG + wq*8192;
    unsigned char* AH = sm;
    unsigned char* WH = sm + 8192;

    // build x1 tile [w=64][h=64] = relu(a1*z1+c1) from bf16 z1
    const unsigned char* ztb = (const unsigned char*)(g_z1b + (size_t)bt*4096);
    #pragma unroll
    for (int it = 0; it < 32; it++) {
        int idx = it*32 + lane;
        int r = idx >> 4, cq = (idx & 15) << 2;
        uint2 u = *(const uint2*)(ztb + (r*64 + cq)*2);
        float4 av = *(float4*)&a1s[cq];
        float4 cv = *(float4*)&c1s[cq];
        float e0 = fmaxf(fmaf(__uint_as_float(u.x << 16),         av.x, cv.x), 0.f);
        float e1 = fmaxf(fmaf(__uint_as_float(u.x & 0xffff0000u), av.y, cv.y), 0.f);
        float e2 = fmaxf(fmaf(__uint_as_float(u.y << 16),         av.z, cv.z), 0.f);
        float e3 = fmaxf(fmaf(__uint_as_float(u.y & 0xffff0000u), av.w, cv.w), 0.f);
        *(uint2*)(XH + toff(r, cq*2)) = make_uint2(packbf(e0, e1), packbf(e2, e3));
    }
    __syncwarp();

    float acc[4][8][4];
    #pragma unroll
    for (int m = 0; m < 4; m++)
        #pragma unroll
        for (int n = 0; n < 8; n++) { acc[m][n][0]=0; acc[m][n][1]=0; acc[m][n][2]=0; acc[m][n][3]=0; }

    // GEMM1: tmp[v][h] = sum_w A[v][w] x1[w][h]  (1-term)
    #pragma unroll
    for (int kt = 0; kt < 4; kt++) {
        uint32_t aH[4][4];
        #pragma unroll
        for (int mt = 0; mt < 4; mt++) lda(aH[mt], AH, mt, kt, lane);
        #pragma unroll
        for (int ntp = 0; ntp < 4; ntp++) {
            uint32_t bq[4];
            ldb4(bq, XH, kt, ntp, lane);
            #pragma unroll
            for (int mt = 0; mt < 4; mt++) {
                mmabf(acc[mt][2*ntp],   aH[mt], bq[0], bq[1]);
                mmabf(acc[mt][2*ntp+1], aH[mt], bq[2], bq[3]);
            }
        }
    }
    __syncwarp();
    // store tmp hi (bf16) over x1 region
    #pragma unroll
    for (int mt = 0; mt < 4; mt++)
        #pragma unroll
        for (int nt = 0; nt < 8; nt++) {
            int r = mt*16 + (lane >> 2), cB = (nt*8 + (lane & 3)*2)*2;
            *(uint32_t*)(XH + toff(r, cB))   = packbf(acc[mt][nt][0], acc[mt][nt][1]);
            *(uint32_t*)(XH + toff(r+8, cB)) = packbf(acc[mt][nt][2], acc[mt][nt][3]);
        }
    __syncwarp();

    // GEMM2: z2[v][o] = sum_h tmp[v][h] W2[h][o]  (1-term)
    #pragma unroll
    for (int m = 0; m < 4; m++)
        #pragma unroll
        for (int n = 0; n < 8; n++) { acc[m][n][0]=0; acc[m][n][1]=0; acc[m][n][2]=0; acc[m][n][3]=0; }
    #pragma unroll
    for (int kt = 0; kt < 4; kt++) {
        uint32_t aH[4][4];
        #pragma unroll
        for (int mt = 0; mt < 4; mt++) lda(aH[mt], XH, mt, kt, lane);
        #pragma unroll
        for (int ntp = 0; ntp < 4; ntp++) {
            uint32_t bq[4];
            ldb4(bq, WH, kt, ntp, lane);
            #pragma unroll
            for (int mt = 0; mt < 4; mt++) {
                mmabf(acc[mt][2*ntp],   aH[mt], bq[0], bq[1]);
                mmabf(acc[mt][2*ntp+1], aH[mt], bq[2], bq[3]);
            }
        }
    }
    __syncwarp();
    epilogue_reg(acc, XH, lane, g_z2b + (size_t)bt*4096, g_psum2, g_psq2, bt);
}

// ---------------- K4: S = sum_t [relu(BN1(z1)) + relu(BN2(z2))]; edges ---------
__global__ void __launch_bounds__(256) k_sumfinal() {
    int bv = blockIdx.x, b = bv >> 6, v = bv & 63;
    int tid = threadIdx.x;
    int hq = (tid & 15) << 2, ph = tid >> 4;     // 16 h-quads x 16 t-phases
    float4 A1 = *(float4*)&g_a1[hq], C1 = *(float4*)&g_c1[hq];
    float4 A2 = *(float4*)&g_a2[hq], C2 = *(float4*)&g_c2[hq];
    float4 s = make_float4(0.f,0.f,0.f,0.f);
    float4 e0 = s, e1 = s;
    #pragma unroll 4
    for (int t = ph; t < TT; t += 16) {
        size_t i1 = (((size_t)(b*TT + t))*64 + v)*64 + hq;
        uint2 u1 = *(const uint2*)&g_z1b[i1];
        uint2 u2 = *(const uint2*)&g_z2b[i1];
        float x0 = fmaxf(fmaf(__uint_as_float(u1.x << 16),         A1.x, C1.x), 0.f)
                 + fmaxf(fmaf(__uint_as_float(u2.x << 16),         A2.x, C2.x), 0.f);
        float x1 = fmaxf(fmaf(__uint_as_float(u1.x & 0xffff0000u), A1.y, C1.y), 0.f)
                 + fmaxf(fmaf(__uint_as_float(u2.x & 0xffff0000u), A2.y, C2.y), 0.f);
        float x2 = fmaxf(fmaf(__uint_as_float(u1.y << 16),         A1.z, C1.z), 0.f)
                 + fmaxf(fmaf(__uint_as_float(u2.y << 16),         A2.z, C2.z), 0.f);
        float x3 = fmaxf(fmaf(__uint_as_float(u1.y & 0xffff0000u), A1.w, C1.w), 0.f)
                 + fmaxf(fmaf(__uint_as_float(u2.y & 0xffff0000u), A2.w, C2.w), 0.f);
        s.x += x0; s.y += x1; s.z += x2; s.w += x3;
        if (t == 0)    e0 = make_float4(x0, x1, x2, x3);
        if (t == TT-1) e1 = make_float4(x0, x1, x2, x3);
    }
    __shared__ float sr[16][64], se0[64], se1[64];
    *(float4*)&sr[ph][hq] = s;
    if (ph == 0)  *(float4*)&se0[hq] = e0;
    if (ph == 15) *(float4*)&se1[hq] = e1;
    __syncthreads();
    if (tid < 64) {
        float S = 0.f;
        #pragma unroll
        for (int p = 0; p < 16; p++) S += sr[p][tid];
        int o = b*4096 + v*64 + tid;
        g_S[o]  = S;
        g_E0[o] = se0[tid];
        g_E1[o] = se1[tid];
    }
}

// ---------------- K5: collapsed conv+mean --------------------------------------
__global__ void __launch_bounds__(256) k_pool(const float* __restrict__ tw,
                                              const float* __restrict__ tb) {
    int o = blockIdx.x, tid = threadIdx.x;
    float acc[BB];
    #pragma unroll
    for (int b = 0; b < BB; b++) acc[b] = 0.f;
    const float* two = tw + (size_t)o*VH*3;
    for (int i = tid; i < VH; i += 256) {
        float t0 = two[i*3+0], t1 = two[i*3+1], t2 = two[i*3+2];
        float ts = t0 + t1 + t2;
        #pragma unroll
        for (int b = 0; b < BB; b++) {
            int ix = b*VH + i;
            acc[b] += ts*g_S[ix] - t0*g_E1[ix] - t2*g_E0[ix];
        }
    }
    __shared__ float red[16][257];
    __shared__ float red2[16][17];
    #pragma unroll
    for (int b = 0; b < BB; b++) red[b][tid] = acc[b];
    __syncthreads();
    int g = tid >> 4, bq = tid & 15;
    float s = 0.f;
    #pragma unroll
    for (int k = 0; k < 16; k++) s += red[bq][g + k*16];
    red2[bq][g] = s;
    __syncthreads();
    if (tid < 16) {
        float tot = 0.f;
        #pragma unroll
        for (int k = 0; k < 16; k++) tot += red2[tid][k];
        g_y[tid*TC + o] = tot*(1.f/TT) + tb[o];
    }
}

// ---------------- K6: FC head ---------------------------------------------------
__global__ void __launch_bounds__(256) k_fc(const float* __restrict__ f1w,
                                            const float* __restrict__ f1b,
                                            const float* __restrict__ f2w,
                                            const float* __restrict__ f2b,
                                            float* __restrict__ out) {
    __shared__ float ys[BB*TC];
    __shared__ float hs[BB*128];
    int tid = threadIdx.x;
    for (int i = tid; i < BB*TC; i += 256) ys[i] = g_y[i];
    __syncthreads();
    int b = tid >> 4, jq = (tid & 15) * 8;
    float acc[8];
    #pragma unroll
    for (int j = 0; j < 8; j++) acc[j] = f1b[jq+j];
    for (int o = 0; o < TC; o++) {
        float yv = ys[b*TC + o];
        const float* w = f1w + o*128 + jq;
        #pragma unroll
        for (int j = 0; j < 8; j++) acc[j] += yv * w[j];
    }
    #pragma unroll
    for (int j = 0; j < 8; j++) hs[b*128 + jq + j] = fmaxf(acc[j], 0.f);
    __syncthreads();
    if (tid < BB*10) {
        int bb = tid / 10, n = tid % 10;
        float s = f2b[n];
        #pragma unroll 8
        for (int j = 0; j < 128; j++) s += hs[bb*128 + j] * f2w[j*10 + n];
        out[tid] = s;
    }
}

// ---------------- launch ---------------------------------------------------------
extern "C" void kernel_launch(void* const* d_in, const int* in_sizes, int n_in,
                              void* d_out, int out_size) {
    const float* x    = (const float*)d_in[0];
    const float* adj  = (const float*)d_in[1];
    const float* w1   = (const float*)d_in[2];
    const float* g1   = (const float*)d_in[4];
    const float* be1  = (const float*)d_in[5];
    const float* w2   = (const float*)d_in[6];
    const float* g2   = (const float*)d_in[8];
    const float* be2  = (const float*)d_in[9];
    const float* tw   = (const float*)d_in[10];
    const float* tb   = (const float*)d_in[11];
    const float* f1w  = (const float*)d_in[12];
    const float* f1b  = (const float*)d_in[13];
    const float* f2w  = (const float*)d_in[14];
    const float* f2b  = (const float*)d_in[15];
    float* out = (float*)d_out;

    cudaFuncSetAttribute(k_l1, cudaFuncAttributeMaxDynamicSharedMemorySize, L1_SM);
    cudaFuncSetAttribute(k_l2, cudaFuncAttributeMaxDynamicSharedMemorySize, L2_SM);

    k_prep<<<BB, 256>>>(adj, w1, w2);
    k_l1<<<BB*128, 128, L1_SM>>>(x);
    k_stats<<<HH, 256>>>(0, g1, be1);
    k_l2<<<BB*128, 128, L2_SM>>>();
    k_stats<<<HH, 256>>>(1, g2, be2);
    k_sumfinal<<<BB*VV, 256>>>();
    k_pool<<<TC, 256>>>(tw, tb);
    k_fc<<<1, 256>>>(f1w, f1b, f2w, f2b, out);
}

// round 12
// speedup vs baseline: 1.7552x; 1.1540x over previous
#include <cuda_runtime.h>
#include <cuda_bf16.h>
#include <cstdint>

#define BB 16
#define TT 512
#define VV 64
#define HH 64
#define BT (BB*TT)
#define VH (VV*HH)
#define TC 256

// ---------------- scratch ----------------------------------------------------
__device__ __nv_bfloat16 g_adjH[BB*4096];                  // swizzled [b][v][w]
__device__ __nv_bfloat16 g_w1H[1024];                      // swizzled [c=16][h=64]
__device__ __nv_bfloat16 g_w2H[4096];                      // swizzled [h][o]
__device__ __nv_bfloat16 g_z1b[(size_t)BT*VH];             // bf16 [bt][v][h]
__device__ __nv_bfloat16 g_z2b[(size_t)BT*VH];             // bf16 [bt][v][o]
__device__ float g_psum1[HH*BT], g_psq1[HH*BT];
__device__ float g_psum2[HH*BT], g_psq2[HH*BT];
__device__ float g_a1[HH], g_c1[HH], g_a2[HH], g_c2[HH];
__device__ float g_S[BB*VH], g_E0[BB*VH], g_E1[BB*VH];
__device__ float g_yp[32*256*16];                          // pool partials
__device__ float g_y[BB*TC];

extern __shared__ unsigned char s_dyn[];

// ---------------- helpers -----------------------------------------------------
__device__ __forceinline__ uint32_t toff(int r, int cB) {
    return (uint32_t)(r*128 + (cB ^ ((r & 7) << 4)));
}
__device__ __forceinline__ void ldsm4(uint32_t* r, unsigned char* p) {
    uint32_t a; asm("{ .reg .u64 t; cvta.to.shared.u64 t, %1; cvt.u32.u64 %0, t; }" : "=r"(a) : "l"(p));
    asm volatile("ldmatrix.sync.aligned.m8n8.x4.shared.b16 {%0,%1,%2,%3}, [%4];"
        : "=r"(r[0]), "=r"(r[1]), "=r"(r[2]), "=r"(r[3]) : "r"(a));
}
__device__ __forceinline__ void ldsm4t(uint32_t* r, unsigned char* p) {
    uint32_t a; asm("{ .reg .u64 t; cvta.to.shared.u64 t, %1; cvt.u32.u64 %0, t; }" : "=r"(a) : "l"(p));
    asm volatile("ldmatrix.sync.aligned.m8n8.x4.trans.shared.b16 {%0,%1,%2,%3}, [%4];"
        : "=r"(r[0]), "=r"(r[1]), "=r"(r[2]), "=r"(r[3]) : "r"(a));
}
__device__ __forceinline__ void mmabf(float* c, const uint32_t* a, uint32_t b0, uint32_t b1) {
    asm volatile("mma.sync.aligned.m16n8k16.row.col.f32.bf16.bf16.f32 "
        "{%0,%1,%2,%3},{%4,%5,%6,%7},{%8,%9},{%0,%1,%2,%3};"
        : "+f"(c[0]), "+f"(c[1]), "+f"(c[2]), "+f"(c[3])
        : "r"(a[0]), "r"(a[1]), "r"(a[2]), "r"(a[3]), "r"(b0), "r"(b1));
}
__device__ __forceinline__ uint32_t packbf(float f0, float f1) {
    uint32_t r;
    asm("cvt.rn.bf16x2.f32 %0, %1, %2;" : "=r"(r) : "f"(f1), "f"(f0));
    return r;
}
__device__ __forceinline__ void lda(uint32_t* a, unsigned char* base, int mt, int kt, int lane) {
    int row = mt*16 + (lane & 7) + (lane & 8);
    int cB  = kt*32 + ((lane >> 4) << 4);
    ldsm4(a, base + toff(row, cB));
}
// B fragments for TWO adjacent n-tiles via x4 trans
__device__ __forceinline__ void ldb4(uint32_t* bq, unsigned char* base, int kt, int ntp, int lane) {
    int g = lane >> 3;
    int row = kt*16 + ((g & 1) << 3) + (lane & 7);
    int cB  = ntp*32 + ((g >> 1) << 4);
    ldsm4t(bq, base + toff(row, cB));
}

// ---------------- K0: prep ----------------------------------------------------
__global__ void k_prep(const float* __restrict__ adj, const float* __restrict__ w1,
                       const float* __restrict__ w2) {
    int b = blockIdx.x, tid = threadIdx.x;
    __shared__ float dis[64];
    const float* A = adj + b*4096;
    if (tid < 64) {
        float s = 0.f;
        #pragma unroll 8
        for (int w = 0; w < 64; w++) s += A[tid*64 + w];
        dis[tid] = rsqrtf(s + 1e-6f);
    }
    __syncthreads();
    for (int idx = tid; idx < 4096; idx += 256) {
        int v = idx >> 6, w = idx & 63;
        float a = dis[v] * A[idx] * dis[w];
        uint32_t e = toff(v, w*2) >> 1;
        g_adjH[b*4096 + e] = __float2bfloat16(a);
    }
    if (b == 0) {
        for (int idx = tid; idx < 1024; idx += 256) {
            int c = idx >> 6, h = idx & 63;
            uint32_t e = toff(c, h*2) >> 1;
            g_w1H[e] = __float2bfloat16(w1[c*64 + h]);
        }
        for (int idx = tid; idx < 4096; idx += 256) {
            int h = idx >> 6, o = idx & 63;
            uint32_t e = toff(h, o*2) >> 1;
            g_w2H[e] = __float2bfloat16(w2[h*64 + o]);
        }
    }
}

// ---------------- register epilogue: shuffle-stats + bf16 stage + store -------
__device__ __forceinline__ void epilogue_reg(float acc[4][8][4], unsigned char* stage, int lane,
                                             __nv_bfloat16* zout, float* psum, float* psq, int bt) {
    #pragma unroll
    for (int nt = 0; nt < 8; nt++) {
        float p0=0.f, p1=0.f, r0=0.f, r1=0.f;
        #pragma unroll
        for (int mt = 0; mt < 4; mt++) {
            float a0=acc[mt][nt][0], a1=acc[mt][nt][1], a2=acc[mt][nt][2], a3=acc[mt][nt][3];
            p0 += a0 + a2; p1 += a1 + a3;
            r0 += a0*a0 + a2*a2; r1 += a1*a1 + a3*a3;
        }
        #pragma unroll
        for (int d = 4; d < 32; d <<= 1) {
            p0 += __shfl_xor_sync(0xffffffffu, p0, d);
            p1 += __shfl_xor_sync(0xffffffffu, p1, d);
            r0 += __shfl_xor_sync(0xffffffffu, r0, d);
            r1 += __shfl_xor_sync(0xffffffffu, r1, d);
        }
        if (lane < 4) {
            int c = nt*8 + lane*2;
            psum[c*BT + bt] = p0; psum[(c+1)*BT + bt] = p1;
            psq[c*BT + bt]  = r0; psq[(c+1)*BT + bt]  = r1;
        }
    }
    #pragma unroll
    for (int mt = 0; mt < 4; mt++)
        #pragma unroll
        for (int nt = 0; nt < 8; nt++) {
            int r = mt*16 + (lane >> 2), cB = (nt*8 + (lane & 3)*2)*2;
            *(uint32_t*)(stage + toff(r, cB))   = packbf(acc[mt][nt][0], acc[mt][nt][1]);
            *(uint32_t*)(stage + toff(r+8, cB)) = packbf(acc[mt][nt][2], acc[mt][nt][3]);
        }
    __syncwarp();
    #pragma unroll
    for (int it = 0; it < 16; it++) {
        int idx = it*32 + lane;
        int r = idx >> 3, cB = (idx & 7) * 16;
        uint4 v = *(uint4*)(stage + toff(r, cB));
        *(uint4*)((unsigned char*)zout + r*128 + cB) = v;
    }
}

// ---------------- K1: layer1 HMMA ----------------------------------------------
// smem: AH 0(8K) W1H 8192(2K) | wreg 10240 + wq*8192
#define L1_WREG 10240
#define L1_SM   (10240 + 4*8192)
__global__ void __launch_bounds__(128, 3) k_l1(const float* __restrict__ x) {
    int blk = blockIdx.x, b = blk >> 7, chunk = blk & 127;
    int tid = threadIdx.x, lane = tid & 31, wq = tid >> 5;
    unsigned char* sm = s_dyn;
    {
        const uint4* s1 = (const uint4*)(g_adjH + b*4096);
        uint4* d1 = (uint4*)sm;
        for (int i = tid; i < 512; i += 128) d1[i] = s1[i];
        const uint4* s3 = (const uint4*)g_w1H;
        uint4* d3 = (uint4*)(sm + 8192);
        if (tid < 128) d3[tid] = s3[tid];
    }
    __syncthreads();

    int t = chunk*4 + wq;
    int bt = b*TT + t;
    unsigned char* XH = sm + L1_WREG + wq*8192;
    unsigned char* AH = sm;
    unsigned char* WH = sm + 8192;

    // build X tile [w=64][c=16] bf16 hi
    const float* xg = x + (size_t)bt*1024;
    #pragma unroll
    for (int it = 0; it < 8; it++) {
        int idx = it*32 + lane;
        int r = idx >> 2, cq = (idx & 3) << 2;
        float4 u = *(const float4*)&xg[r*16 + cq];
        *(uint2*)(XH + toff(r, cq*2)) = make_uint2(packbf(u.x, u.y), packbf(u.z, u.w));
    }
    __syncwarp();

    // GEMM1': tmp[v][c] = sum_w A[v][w] X[w][c]  (1-term)
    float acc1[4][2][4];
    #pragma unroll
    for (int m = 0; m < 4; m++)
        #pragma unroll
        for (int n = 0; n < 2; n++) { acc1[m][n][0]=0; acc1[m][n][1]=0; acc1[m][n][2]=0; acc1[m][n][3]=0; }
    #pragma unroll
    for (int kt = 0; kt < 4; kt++) {
        uint32_t aH[4][4], bq[4];
        #pragma unroll
        for (int mt = 0; mt < 4; mt++) lda(aH[mt], AH, mt, kt, lane);
        ldb4(bq, XH, kt, 0, lane);
        #pragma unroll
        for (int mt = 0; mt < 4; mt++) {
            mmabf(acc1[mt][0], aH[mt], bq[0], bq[1]);
            mmabf(acc1[mt][1], aH[mt], bq[2], bq[3]);
        }
    }
    __syncwarp();
    // store tmp hi (bf16) over X region
    #pragma unroll
    for (int mt = 0; mt < 4; mt++)
        #pragma unroll
        for (int nt = 0; nt < 2; nt++) {
            int r = mt*16 + (lane >> 2), cB = (nt*8 + (lane & 3)*2)*2;
            *(uint32_t*)(XH + toff(r, cB))   = packbf(acc1[mt][nt][0], acc1[mt][nt][1]);
            *(uint32_t*)(XH + toff(r+8, cB)) = packbf(acc1[mt][nt][2], acc1[mt][nt][3]);
        }
    __syncwarp();

    // GEMM2': z1[v][h] = sum_c tmp[v][c] W1[c][h]  (1-term)
    float acc2[4][8][4];
    #pragma unroll
    for (int m = 0; m < 4; m++)
        #pragma unroll
        for (int n = 0; n < 8; n++) { acc2[m][n][0]=0; acc2[m][n][1]=0; acc2[m][n][2]=0; acc2[m][n][3]=0; }
    {
        uint32_t aH[4][4];
        #pragma unroll
        for (int mt = 0; mt < 4; mt++) lda(aH[mt], XH, mt, 0, lane);
        #pragma unroll
        for (int ntp = 0; ntp < 4; ntp++) {
            uint32_t bq[4];
            ldb4(bq, WH, 0, ntp, lane);
            #pragma unroll
            for (int mt = 0; mt < 4; mt++) {
                mmabf(acc2[mt][2*ntp],   aH[mt], bq[0], bq[1]);
                mmabf(acc2[mt][2*ntp+1], aH[mt], bq[2], bq[3]);
            }
        }
    }
    __syncwarp();
    epilogue_reg(acc2, XH, lane, g_z1b + (size_t)bt*4096, g_psum1, g_psq1, bt);
}

// ---------------- K2: finalize BN affine ---------------------------------------
__global__ void k_stats(int layer, const float* __restrict__ g, const float* __restrict__ be) {
    int h = blockIdx.x, tid = threadIdx.x;
    const float* ps = layer ? g_psum2 : g_psum1;
    const float* pq = layer ? g_psq2  : g_psq1;
    __shared__ float ss[256], sq[256];
    float s = 0.f, q = 0.f;
    for (int i = tid; i < BT; i += 256) { s += ps[h*BT + i]; q += pq[h*BT + i]; }
    ss[tid] = s; sq[tid] = q;
    __syncthreads();
    for (int st = 128; st > 0; st >>= 1) {
        if (tid < st) { ss[tid] += ss[tid+st]; sq[tid] += sq[tid+st]; }
        __syncthreads();
    }
    if (tid == 0) {
        const float N = (float)(BT*VV);
        float mean = ss[0] / N;
        float var  = sq[0] / N - mean*mean;
        float av = g[h] * rsqrtf(var + 1e-5f);
        if (layer) { g_a2[h] = av; g_c2[h] = be[h] - mean*av; }
        else       { g_a1[h] = av; g_c1[h] = be[h] - mean*av; }
    }
}

// ---------------- K3: layer2 HMMA ----------------------------------------------
// smem: AH 0(8K) W2H 8192(8K) a1/c1 16384(512B) | wreg 16896 + wq*8192
#define L2_WREG 16896
#define L2_SM   (16896 + 4*8192)
__global__ void __launch_bounds__(128, 3) k_l2() {
    int blk = blockIdx.x, b = blk >> 7, chunk = blk & 127;
    int tid = threadIdx.x, lane = tid & 31, wq = tid >> 5;
    unsigned char* sm = s_dyn;
    float* a1s = (float*)(sm + 16384);
    float* c1s = a1s + 64;
    {
        const uint4* s1 = (const uint4*)(g_adjH + b*4096);
        uint4* d1 = (uint4*)sm;
        for (int i = tid; i < 512; i += 128) d1[i] = s1[i];
        const uint4* s3 = (const uint4*)g_w2H;
        uint4* d3 = (uint4*)(sm + 8192);
        for (int i = tid; i < 512; i += 128) d3[i] = s3[i];
        if (tid < 64) { a1s[tid] = g_a1[tid]; c1s[tid] = g_c1[tid]; }
    }
    __syncthreads();

    int t = chunk*4 + wq;
    int bt = b*TT + t;
    unsigned char* XH = sm + L2_WREG + wq*8192;
    unsigned char* AH = sm;
    unsigned char* WH = sm + 8192;

    // build x1 tile [w=64][h=64] = relu(a1*z1+c1) from bf16 z1
    const unsigned char* ztb = (const unsigned char*)(g_z1b + (size_t)bt*4096);
    #pragma unroll
    for (int it = 0; it < 32; it++) {
        int idx = it*32 + lane;
        int r = idx >> 4, cq = (idx & 15) << 2;
        uint2 u = *(const uint2*)(ztb + (r*64 + cq)*2);
        float4 av = *(float4*)&a1s[cq];
        float4 cv = *(float4*)&c1s[cq];
        float e0 = fmaxf(fmaf(__uint_as_float(u.x << 16),         av.x, cv.x), 0.f);
        float e1 = fmaxf(fmaf(__uint_as_float(u.x & 0xffff0000u), av.y, cv.y), 0.f);
        float e2 = fmaxf(fmaf(__uint_as_float(u.y << 16),         av.z, cv.z), 0.f);
        float e3 = fmaxf(fmaf(__uint_as_float(u.y & 0xffff0000u), av.w, cv.w), 0.f);
        *(uint2*)(XH + toff(r, cq*2)) = make_uint2(packbf(e0, e1), packbf(e2, e3));
    }
    __syncwarp();

    float acc[4][8][4];
    #pragma unroll
    for (int m = 0; m < 4; m++)
        #pragma unroll
        for (int n = 0; n < 8; n++) { acc[m][n][0]=0; acc[m][n][1]=0; acc[m][n][2]=0; acc[m][n][3]=0; }

    // GEMM1: tmp[v][h] = sum_w A[v][w] x1[w][h]  (1-term)
    #pragma unroll
    for (int kt = 0; kt < 4; kt++) {
        uint32_t aH[4][4];
        #pragma unroll
        for (int mt = 0; mt < 4; mt++) lda(aH[mt], AH, mt, kt, lane);
        #pragma unroll
        for (int ntp = 0; ntp < 4; ntp++) {
            uint32_t bq[4];
            ldb4(bq, XH, kt, ntp, lane);
            #pragma unroll
            for (int mt = 0; mt < 4; mt++) {
                mmabf(acc[mt][2*ntp],   aH[mt], bq[0], bq[1]);
                mmabf(acc[mt][2*ntp+1], aH[mt], bq[2], bq[3]);
            }
        }
    }
    __syncwarp();
    // store tmp hi (bf16) over x1 region
    #pragma unroll
    for (int mt = 0; mt < 4; mt++)
        #pragma unroll
        for (int nt = 0; nt < 8; nt++) {
            int r = mt*16 + (lane >> 2), cB = (nt*8 + (lane & 3)*2)*2;
            *(uint32_t*)(XH + toff(r, cB))   = packbf(acc[mt][nt][0], acc[mt][nt][1]);
            *(uint32_t*)(XH + toff(r+8, cB)) = packbf(acc[mt][nt][2], acc[mt][nt][3]);
        }
    __syncwarp();

    // GEMM2: z2[v][o] = sum_h tmp[v][h] W2[h][o]  (1-term)
    #pragma unroll
    for (int m = 0; m < 4; m++)
        #pragma unroll
        for (int n = 0; n < 8; n++) { acc[m][n][0]=0; acc[m][n][1]=0; acc[m][n][2]=0; acc[m][n][3]=0; }
    #pragma unroll
    for (int kt = 0; kt < 4; kt++) {
        uint32_t aH[4][4];
        #pragma unroll
        for (int mt = 0; mt < 4; mt++) lda(aH[mt], XH, mt, kt, lane);
        #pragma unroll
        for (int ntp = 0; ntp < 4; ntp++) {
            uint32_t bq[4];
            ldb4(bq, WH, kt, ntp, lane);
            #pragma unroll
            for (int mt = 0; mt < 4; mt++) {
                mmabf(acc[mt][2*ntp],   aH[mt], bq[0], bq[1]);
                mmabf(acc[mt][2*ntp+1], aH[mt], bq[2], bq[3]);
            }
        }
    }
    __syncwarp();
    epilogue_reg(acc, XH, lane, g_z2b + (size_t)bt*4096, g_psum2, g_psq2, bt);
}

// ---------------- K4: S = sum_t [relu(BN1(z1)) + relu(BN2(z2))]; edges ---------
__global__ void __launch_bounds__(256) k_sumfinal() {
    int bv = blockIdx.x, b = bv >> 6, v = bv & 63;
    int tid = threadIdx.x;
    int hq = (tid & 15) << 2, ph = tid >> 4;
    float4 A1 = *(float4*)&g_a1[hq], C1 = *(float4*)&g_c1[hq];
    float4 A2 = *(float4*)&g_a2[hq], C2 = *(float4*)&g_c2[hq];
    float4 s = make_float4(0.f,0.f,0.f,0.f);
    float4 e0 = s, e1 = s;
    #pragma unroll 4
    for (int t = ph; t < TT; t += 16) {
        size_t i1 = (((size_t)(b*TT + t))*64 + v)*64 + hq;
        uint2 u1 = *(const uint2*)&g_z1b[i1];
        uint2 u2 = *(const uint2*)&g_z2b[i1];
        float x0 = fmaxf(fmaf(__uint_as_float(u1.x << 16),         A1.x, C1.x), 0.f)
                 + fmaxf(fmaf(__uint_as_float(u2.x << 16),         A2.x, C2.x), 0.f);
        float x1 = fmaxf(fmaf(__uint_as_float(u1.x & 0xffff0000u), A1.y, C1.y), 0.f)
                 + fmaxf(fmaf(__uint_as_float(u2.x & 0xffff0000u), A2.y, C2.y), 0.f);
        float x2 = fmaxf(fmaf(__uint_as_float(u1.y << 16),         A1.z, C1.z), 0.f)
                 + fmaxf(fmaf(__uint_as_float(u2.y << 16),         A2.z, C2.z), 0.f);
        float x3 = fmaxf(fmaf(__uint_as_float(u1.y & 0xffff0000u), A1.w, C1.w), 0.f)
                 + fmaxf(fmaf(__uint_as_float(u2.y & 0xffff0000u), A2.w, C2.w), 0.f);
        s.x += x0; s.y += x1; s.z += x2; s.w += x3;
        if (t == 0)    e0 = make_float4(x0, x1, x2, x3);
        if (t == TT-1) e1 = make_float4(x0, x1, x2, x3);
    }
    __shared__ float sr[16][64], se0[64], se1[64];
    *(float4*)&sr[ph][hq] = s;
    if (ph == 0)  *(float4*)&se0[hq] = e0;
    if (ph == 15) *(float4*)&se1[hq] = e1;
    __syncthreads();
    if (tid < 64) {
        float S = 0.f;
        #pragma unroll
        for (int p = 0; p < 16; p++) S += sr[p][tid];
        int o = b*4096 + v*64 + tid;
        g_S[o]  = S;
        g_E0[o] = se0[tid];
        g_E1[o] = se1[tid];
    }
}

// ---------------- K5a: pool partials (i-tiles x o-tiles) ----------------------
__global__ void __launch_bounds__(256) k_poolA(const float* __restrict__ tw) {
    int itile = blockIdx.x;   // 0..31 (128 i each)
    int otile = blockIdx.y;   // 0..15 (16 o each)
    int tid = threadIdx.x, lane = tid & 31, wq = tid >> 5;
    __shared__ float sS[16][128], sE0[16][128], sE1[16][128];
    int i0 = itile*128;
    #pragma unroll
    for (int k = 0; k < 2; k++) {
        int i4 = k*256 + tid;
        int b = i4 >> 5, ii = (i4 & 31) << 2;
        *(float4*)&sS[b][ii]  = *(const float4*)&g_S [b*4096 + i0 + ii];
        *(float4*)&sE0[b][ii] = *(const float4*)&g_E0[b*4096 + i0 + ii];
        *(float4*)&sE1[b][ii] = *(const float4*)&g_E1[b*4096 + i0 + ii];
    }
    __syncthreads();
    #pragma unroll
    for (int pass = 0; pass < 2; pass++) {
        int o = otile*16 + pass*8 + wq;
        float acc[16];
        #pragma unroll
        for (int b = 0; b < 16; b++) acc[b] = 0.f;
        #pragma unroll
        for (int k = 0; k < 4; k++) {
            int i = k*32 + lane;
            const float* twp = tw + ((size_t)o*4096 + i0 + i)*3;
            float t0 = twp[0], t1 = twp[1], t2 = twp[2];
            float ts = t0 + t1 + t2;
            #pragma unroll
            for (int b = 0; b < 16; b++)
                acc[b] += ts*sS[b][i] - t0*sE1[b][i] - t2*sE0[b][i];
        }
        float mine = 0.f;
        #pragma unroll
        for (int b = 0; b < 16; b++) {
            float v = acc[b];
            #pragma unroll
            for (int d = 16; d > 0; d >>= 1) v += __shfl_xor_sync(0xffffffffu, v, d);
            if (lane == b) mine = v;
        }
        if (lane < 16) g_yp[((size_t)itile*256 + o)*16 + lane] = mine;
    }
}

// ---------------- K5b: reduce pool partials ------------------------------------
__global__ void __launch_bounds__(256) k_poolB(const float* __restrict__ tb) {
    int tid = threadIdx.x;
    int o = blockIdx.x*16 + (tid >> 4);
    int b = tid & 15;
    float s = 0.f;
    #pragma unroll 8
    for (int it = 0; it < 32; it++) s += g_yp[((size_t)it*256 + o)*16 + b];
    g_y[b*TC + o] = s*(1.f/TT) + tb[o];
}

// ---------------- K6: FC head ---------------------------------------------------
__global__ void __launch_bounds__(256) k_fc(const float* __restrict__ f1w,
                                            const float* __restrict__ f1b,
                                            const float* __restrict__ f2w,
                                            const float* __restrict__ f2b,
                                            float* __restrict__ out) {
    __shared__ float ys[BB*TC];
    __shared__ float hs[BB*128];
    int tid = threadIdx.x;
    for (int i = tid; i < BB*TC; i += 256) ys[i] = g_y[i];
    __syncthreads();
    int b = tid >> 4, jq = (tid & 15) * 8;
    float acc[8];
    #pragma unroll
    for (int j = 0; j < 8; j++) acc[j] = f1b[jq+j];
    for (int o = 0; o < TC; o++) {
        float yv = ys[b*TC + o];
        const float* w = f1w + o*128 + jq;
        #pragma unroll
        for (int j = 0; j < 8; j++) acc[j] += yv * w[j];
    }
    #pragma unroll
    for (int j = 0; j < 8; j++) hs[b*128 + jq + j] = fmaxf(acc[j], 0.f);
    __syncthreads();
    if (tid < BB*10) {
        int bb = tid / 10, n = tid % 10;
        float s = f2b[n];
        #pragma unroll 8
        for (int j = 0; j < 128; j++) s += hs[bb*128 + j] * f2w[j*10 + n];
        out[tid] = s;
    }
}

// ---------------- launch ---------------------------------------------------------
extern "C" void kernel_launch(void* const* d_in, const int* in_sizes, int n_in,
                              void* d_out, int out_size) {
    const float* x    = (const float*)d_in[0];
    const float* adj  = (const float*)d_in[1];
    const float* w1   = (const float*)d_in[2];
    const float* g1   = (const float*)d_in[4];
    const float* be1  = (const float*)d_in[5];
    const float* w2   = (const float*)d_in[6];
    const float* g2   = (const float*)d_in[8];
    const float* be2  = (const float*)d_in[9];
    const float* tw   = (const float*)d_in[10];
    const float* tb   = (const float*)d_in[11];
    const float* f1w  = (const float*)d_in[12];
    const float* f1b  = (const float*)d_in[13];
    const float* f2w  = (const float*)d_in[14];
    const float* f2b  = (const float*)d_in[15];
    float* out = (float*)d_out;

    cudaFuncSetAttribute(k_l1, cudaFuncAttributeMaxDynamicSharedMemorySize, L1_SM);
    cudaFuncSetAttribute(k_l2, cudaFuncAttributeMaxDynamicSharedMemorySize, L2_SM);

    k_prep<<<BB, 256>>>(adj, w1, w2);
    k_l1<<<BB*128, 128, L1_SM>>>(x);
    k_stats<<<HH, 256>>>(0, g1, be1);
    k_l2<<<BB*128, 128, L2_SM>>>();
    k_stats<<<HH, 256>>>(1, g2, be2);
    k_sumfinal<<<BB*VV, 256>>>();
    dim3 gp(32, 16);
    k_poolA<<<gp, 256>>>(tw);
    k_poolB<<<16, 256>>>(tb);
    k_fc<<<1, 256>>>(f1w, f1b, f2w, f2b, out);
}

// round 13
// speedup vs baseline: 1.7691x; 1.0079x over previous
#include <cuda_runtime.h>
#include <cuda_bf16.h>
#include <cstdint>

#define BB 16
#define TT 512
#define VV 64
#define HH 64
#define BT (BB*TT)
#define VH (VV*HH)
#define TC 256

// ---------------- scratch ----------------------------------------------------
__device__ __nv_bfloat16 g_adjH[BB*4096];                  // swizzled [b][v][w]
__device__ __nv_bfloat16 g_w1H[1024];                      // swizzled [c=16][h=64]
__device__ __nv_bfloat16 g_w2H[4096];                      // swizzled [h][o]
__device__ __nv_bfloat16 g_z1b[(size_t)BT*VH];             // bf16 [bt][v][h]
__device__ __nv_bfloat16 g_z2b[(size_t)BT*VH];             // bf16 [bt][v][o]
__device__ float g_psum1[BT*HH], g_psq1[BT*HH];            // [bt][h]
__device__ float g_psum2[BT*HH], g_psq2[BT*HH];
__device__ float g_a1[HH], g_c1[HH], g_a2[HH], g_c2[HH];
__device__ float g_S[BB*VH], g_E0[BB*VH], g_E1[BB*VH];
__device__ float g_yp[32*256*16];                          // pool partials
__device__ float g_y[BB*TC];

extern __shared__ unsigned char s_dyn[];

// ---------------- helpers -----------------------------------------------------
__device__ __forceinline__ uint32_t toff(int r, int cB) {
    return (uint32_t)(r*128 + (cB ^ ((r & 7) << 4)));
}
__device__ __forceinline__ void ldsm4(uint32_t* r, unsigned char* p) {
    uint32_t a; asm("{ .reg .u64 t; cvta.to.shared.u64 t, %1; cvt.u32.u64 %0, t; }" : "=r"(a) : "l"(p));
    asm volatile("ldmatrix.sync.aligned.m8n8.x4.shared.b16 {%0,%1,%2,%3}, [%4];"
        : "=r"(r[0]), "=r"(r[1]), "=r"(r[2]), "=r"(r[3]) : "r"(a));
}
__device__ __forceinline__ void ldsm4t(uint32_t* r, unsigned char* p) {
    uint32_t a; asm("{ .reg .u64 t; cvta.to.shared.u64 t, %1; cvt.u32.u64 %0, t; }" : "=r"(a) : "l"(p));
    asm volatile("ldmatrix.sync.aligned.m8n8.x4.trans.shared.b16 {%0,%1,%2,%3}, [%4];"
        : "=r"(r[0]), "=r"(r[1]), "=r"(r[2]), "=r"(r[3]) : "r"(a));
}
__device__ __forceinline__ void mmabf(float* c, const uint32_t* a, uint32_t b0, uint32_t b1) {
    asm volatile("mma.sync.aligned.m16n8k16.row.col.f32.bf16.bf16.f32 "
        "{%0,%1,%2,%3},{%4,%5,%6,%7},{%8,%9},{%0,%1,%2,%3};"
        : "+f"(c[0]), "+f"(c[1]), "+f"(c[2]), "+f"(c[3])
        : "r"(a[0]), "r"(a[1]), "r"(a[2]), "r"(a[3]), "r"(b0), "r"(b1));
}
__device__ __forceinline__ uint32_t packbf(float f0, float f1) {
    uint32_t r;
    asm("cvt.rn.bf16x2.f32 %0, %1, %2;" : "=r"(r) : "f"(f1), "f"(f0));
    return r;
}
// fused bf16x2 fma + relu
__device__ __forceinline__ uint32_t fmarelu2(uint32_t z, uint32_t a, uint32_t c) {
    uint32_t r;
    asm("fma.rn.relu.bf16x2 %0, %1, %2, %3;" : "=r"(r) : "r"(z), "r"(a), "r"(c));
    return r;
}
__device__ __forceinline__ void lda(uint32_t* a, unsigned char* base, int mt, int kt, int lane) {
    int row = mt*16 + (lane & 7) + (lane & 8);
    int cB  = kt*32 + ((lane >> 4) << 4);
    ldsm4(a, base + toff(row, cB));
}
// B fragments for TWO adjacent n-tiles via x4 trans
__device__ __forceinline__ void ldb4(uint32_t* bq, unsigned char* base, int kt, int ntp, int lane) {
    int g = lane >> 3;
    int row = kt*16 + ((g & 1) << 3) + (lane & 7);
    int cB  = ntp*32 + ((g >> 1) << 4);
    ldsm4t(bq, base + toff(row, cB));
}

// ---------------- K0: prep ----------------------------------------------------
__global__ void k_prep(const float* __restrict__ adj, const float* __restrict__ w1,
                       const float* __restrict__ w2) {
    int b = blockIdx.x, tid = threadIdx.x;
    __shared__ float dis[64];
    const float* A = adj + b*4096;
    if (tid < 64) {
        float s = 0.f;
        #pragma unroll 8
        for (int w = 0; w < 64; w++) s += A[tid*64 + w];
        dis[tid] = rsqrtf(s + 1e-6f);
    }
    __syncthreads();
    for (int idx = tid; idx < 4096; idx += 256) {
        int v = idx >> 6, w = idx & 63;
        float a = dis[v] * A[idx] * dis[w];
        uint32_t e = toff(v, w*2) >> 1;
        g_adjH[b*4096 + e] = __float2bfloat16(a);
    }
    if (b == 0) {
        for (int idx = tid; idx < 1024; idx += 256) {
            int c = idx >> 6, h = idx & 63;
            uint32_t e = toff(c, h*2) >> 1;
            g_w1H[e] = __float2bfloat16(w1[c*64 + h]);
        }
        for (int idx = tid; idx < 4096; idx += 256) {
            int h = idx >> 6, o = idx & 63;
            uint32_t e = toff(h, o*2) >> 1;
            g_w2H[e] = __float2bfloat16(w2[h*64 + o]);
        }
    }
}

// ---------------- register epilogue: shuffle-stats + bf16 stage + store -------
__device__ __forceinline__ void epilogue_reg(float acc[4][8][4], unsigned char* stage, int lane,
                                             __nv_bfloat16* zout, float* psum, float* psq, int bt) {
    #pragma unroll
    for (int nt = 0; nt < 8; nt++) {
        float p0=0.f, p1=0.f, r0=0.f, r1=0.f;
        #pragma unroll
        for (int mt = 0; mt < 4; mt++) {
            float a0=acc[mt][nt][0], a1=acc[mt][nt][1], a2=acc[mt][nt][2], a3=acc[mt][nt][3];
            p0 += a0 + a2; p1 += a1 + a3;
            r0 += a0*a0 + a2*a2; r1 += a1*a1 + a3*a3;
        }
        #pragma unroll
        for (int d = 4; d < 32; d <<= 1) {
            p0 += __shfl_xor_sync(0xffffffffu, p0, d);
            p1 += __shfl_xor_sync(0xffffffffu, p1, d);
            r0 += __shfl_xor_sync(0xffffffffu, r0, d);
            r1 += __shfl_xor_sync(0xffffffffu, r1, d);
        }
        if (lane < 4) {       // coalesced: 8 consecutive floats per nt
            int c = nt*8 + lane*2;
            *(float2*)&psum[bt*64 + c] = make_float2(p0, p1);
            *(float2*)&psq [bt*64 + c] = make_float2(r0, r1);
        }
    }
    #pragma unroll
    for (int mt = 0; mt < 4; mt++)
        #pragma unroll
        for (int nt = 0; nt < 8; nt++) {
            int r = mt*16 + (lane >> 2), cB = (nt*8 + (lane & 3)*2)*2;
            *(uint32_t*)(stage + toff(r, cB))   = packbf(acc[mt][nt][0], acc[mt][nt][1]);
            *(uint32_t*)(stage + toff(r+8, cB)) = packbf(acc[mt][nt][2], acc[mt][nt][3]);
        }
    __syncwarp();
    #pragma unroll
    for (int it = 0; it < 16; it++) {
        int idx = it*32 + lane;
        int r = idx >> 3, cB = (idx & 7) * 16;
        uint4 v = *(uint4*)(stage + toff(r, cB));
        *(uint4*)((unsigned char*)zout + r*128 + cB) = v;
    }
}

// ---------------- K1: layer1 HMMA ----------------------------------------------
// smem: AH 0(8K) W1H 8192(2K) | wreg 10240 + wq*8192
#define L1_WREG 10240
#define L1_SM   (10240 + 4*8192)
__global__ void __launch_bounds__(128, 3) k_l1(const float* __restrict__ x) {
    int blk = blockIdx.x, b = blk >> 7, chunk = blk & 127;
    int tid = threadIdx.x, lane = tid & 31, wq = tid >> 5;
    unsigned char* sm = s_dyn;
    {
        const uint4* s1 = (const uint4*)(g_adjH + b*4096);
        uint4* d1 = (uint4*)sm;
        for (int i = tid; i < 512; i += 128) d1[i] = s1[i];
        const uint4* s3 = (const uint4*)g_w1H;
        uint4* d3 = (uint4*)(sm + 8192);
        if (tid < 128) d3[tid] = s3[tid];
    }
    __syncthreads();

    int t = chunk*4 + wq;
    int bt = b*TT + t;
    unsigned char* XH = sm + L1_WREG + wq*8192;
    unsigned char* AH = sm;
    unsigned char* WH = sm + 8192;

    // build X tile [w=64][c=16] bf16 hi
    const float* xg = x + (size_t)bt*1024;
    #pragma unroll
    for (int it = 0; it < 8; it++) {
        int idx = it*32 + lane;
        int r = idx >> 2, cq = (idx & 3) << 2;
        float4 u = *(const float4*)&xg[r*16 + cq];
        *(uint2*)(XH + toff(r, cq*2)) = make_uint2(packbf(u.x, u.y), packbf(u.z, u.w));
    }
    __syncwarp();

    // GEMM1': tmp[v][c] = sum_w A[v][w] X[w][c]  (1-term)
    float acc1[4][2][4];
    #pragma unroll
    for (int m = 0; m < 4; m++)
        #pragma unroll
        for (int n = 0; n < 2; n++) { acc1[m][n][0]=0; acc1[m][n][1]=0; acc1[m][n][2]=0; acc1[m][n][3]=0; }
    #pragma unroll
    for (int kt = 0; kt < 4; kt++) {
        uint32_t aH[4][4], bq[4];
        #pragma unroll
        for (int mt = 0; mt < 4; mt++) lda(aH[mt], AH, mt, kt, lane);
        ldb4(bq, XH, kt, 0, lane);
        #pragma unroll
        for (int mt = 0; mt < 4; mt++) {
            mmabf(acc1[mt][0], aH[mt], bq[0], bq[1]);
            mmabf(acc1[mt][1], aH[mt], bq[2], bq[3]);
        }
    }
    __syncwarp();
    #pragma unroll
    for (int mt = 0; mt < 4; mt++)
        #pragma unroll
        for (int nt = 0; nt < 2; nt++) {
            int r = mt*16 + (lane >> 2), cB = (nt*8 + (lane & 3)*2)*2;
            *(uint32_t*)(XH + toff(r, cB))   = packbf(acc1[mt][nt][0], acc1[mt][nt][1]);
            *(uint32_t*)(XH + toff(r+8, cB)) = packbf(acc1[mt][nt][2], acc1[mt][nt][3]);
        }
    __syncwarp();

    // GEMM2': z1[v][h] = sum_c tmp[v][c] W1[c][h]  (1-term)
    float acc2[4][8][4];
    #pragma unroll
    for (int m = 0; m < 4; m++)
        #pragma unroll
        for (int n = 0; n < 8; n++) { acc2[m][n][0]=0; acc2[m][n][1]=0; acc2[m][n][2]=0; acc2[m][n][3]=0; }
    {
        uint32_t aH[4][4];
        #pragma unroll
        for (int mt = 0; mt < 4; mt++) lda(aH[mt], XH, mt, 0, lane);
        #pragma unroll
        for (int ntp = 0; ntp < 4; ntp++) {
            uint32_t bq[4];
            ldb4(bq, WH, 0, ntp, lane);
            #pragma unroll
            for (int mt = 0; mt < 4; mt++) {
                mmabf(acc2[mt][2*ntp],   aH[mt], bq[0], bq[1]);
                mmabf(acc2[mt][2*ntp+1], aH[mt], bq[2], bq[3]);
            }
        }
    }
    __syncwarp();
    epilogue_reg(acc2, XH, lane, g_z1b + (size_t)bt*4096, g_psum1, g_psq1, bt);
}

// ---------------- K2: finalize BN affine ---------------------------------------
__global__ void k_stats(int layer, const float* __restrict__ g, const float* __restrict__ be) {
    int h = blockIdx.x, tid = threadIdx.x;
    const float* ps = layer ? g_psum2 : g_psum1;
    const float* pq = layer ? g_psq2  : g_psq1;
    __shared__ float ss[256], sq[256];
    float s = 0.f, q = 0.f;
    for (int i = tid; i < BT; i += 256) { s += ps[i*64 + h]; q += pq[i*64 + h]; }
    ss[tid] = s; sq[tid] = q;
    __syncthreads();
    for (int st = 128; st > 0; st >>= 1) {
        if (tid < st) { ss[tid] += ss[tid+st]; sq[tid] += sq[tid+st]; }
        __syncthreads();
    }
    if (tid == 0) {
        const float N = (float)(BT*VV);
        float mean = ss[0] / N;
        float var  = sq[0] / N - mean*mean;
        float av = g[h] * rsqrtf(var + 1e-5f);
        if (layer) { g_a2[h] = av; g_c2[h] = be[h] - mean*av; }
        else       { g_a1[h] = av; g_c1[h] = be[h] - mean*av; }
    }
}

// ---------------- K3: layer2 HMMA ----------------------------------------------
// smem: AH 0(8K) W2H 8192(8K) a1p/c1p 16384(256B) | wreg 16640 + wq*8192
#define L2_WREG 16640
#define L2_SM   (16640 + 4*8192)
__global__ void __launch_bounds__(128, 3) k_l2() {
    int blk = blockIdx.x, b = blk >> 7, chunk = blk & 127;
    int tid = threadIdx.x, lane = tid & 31, wq = tid >> 5;
    unsigned char* sm = s_dyn;
    uint32_t* a1p = (uint32_t*)(sm + 16384);   // 32 bf16x2 pairs
    uint32_t* c1p = a1p + 32;
    {
        const uint4* s1 = (const uint4*)(g_adjH + b*4096);
        uint4* d1 = (uint4*)sm;
        for (int i = tid; i < 512; i += 128) d1[i] = s1[i];
        const uint4* s3 = (const uint4*)g_w2H;
        uint4* d3 = (uint4*)(sm + 8192);
        for (int i = tid; i < 512; i += 128) d3[i] = s3[i];
        if (tid < 32) {
            a1p[tid] = packbf(g_a1[2*tid], g_a1[2*tid+1]);
            c1p[tid] = packbf(g_c1[2*tid], g_c1[2*tid+1]);
        }
    }
    __syncthreads();

    int t = chunk*4 + wq;
    int bt = b*TT + t;
    unsigned char* XH = sm + L2_WREG + wq*8192;
    unsigned char* AH = sm;
    unsigned char* WH = sm + 8192;

    // build x1 tile [w=64][h=64] = relu(a1*z1+c1), fused bf16x2 fma+relu
    const unsigned char* ztb = (const unsigned char*)(g_z1b + (size_t)bt*4096);
    #pragma unroll
    for (int it = 0; it < 32; it++) {
        int idx = it*32 + lane;
        int r = idx >> 4, cq = (idx & 15) << 2;
        uint2 u = *(const uint2*)(ztb + (r*64 + cq)*2);
        uint32_t v0 = fmarelu2(u.x, a1p[cq >> 1],       c1p[cq >> 1]);
        uint32_t v1 = fmarelu2(u.y, a1p[(cq >> 1) + 1], c1p[(cq >> 1) + 1]);
        *(uint2*)(XH + toff(r, cq*2)) = make_uint2(v0, v1);
    }
    __syncwarp();

    float acc[4][8][4];
    #pragma unroll
    for (int m = 0; m < 4; m++)
        #pragma unroll
        for (int n = 0; n < 8; n++) { acc[m][n][0]=0; acc[m][n][1]=0; acc[m][n][2]=0; acc[m][n][3]=0; }

    // GEMM1: tmp[v][h] = sum_w A[v][w] x1[w][h]  (1-term)
    #pragma unroll
    for (int kt = 0; kt < 4; kt++) {
        uint32_t aH[4][4];
        #pragma unroll
        for (int mt = 0; mt < 4; mt++) lda(aH[mt], AH, mt, kt, lane);
        #pragma unroll
        for (int ntp = 0; ntp < 4; ntp++) {
            uint32_t bq[4];
            ldb4(bq, XH, kt, ntp, lane);
            #pragma unroll
            for (int mt = 0; mt < 4; mt++) {
                mmabf(acc[mt][2*ntp],   aH[mt], bq[0], bq[1]);
                mmabf(acc[mt][2*ntp+1], aH[mt], bq[2], bq[3]);
            }
        }
    }
    __syncwarp();
    // store tmp hi (bf16) over x1 region
    #pragma unroll
    for (int mt = 0; mt < 4; mt++)
        #pragma unroll
        for (int nt = 0; nt < 8; nt++) {
            int r = mt*16 + (lane >> 2), cB = (nt*8 + (lane & 3)*2)*2;
            *(uint32_t*)(XH + toff(r, cB))   = packbf(acc[mt][nt][0], acc[mt][nt][1]);
            *(uint32_t*)(XH + toff(r+8, cB)) = packbf(acc[mt][nt][2], acc[mt][nt][3]);
        }
    __syncwarp();

    // GEMM2: z2[v][o] = sum_h tmp[v][h] W2[h][o]  (1-term)
    #pragma unroll
    for (int m = 0; m < 4; m++)
        #pragma unroll
        for (int n = 0; n < 8; n++) { acc[m][n][0]=0; acc[m][n][1]=0; acc[m][n][2]=0; acc[m][n][3]=0; }
    #pragma unroll
    for (int kt = 0; kt < 4; kt++) {
        uint32_t aH[4][4];
        #pragma unroll
        for (int mt = 0; mt < 4; mt++) lda(aH[mt], XH, mt, kt, lane);
        #pragma unroll
        for (int ntp = 0; ntp < 4; ntp++) {
            uint32_t bq[4];
            ldb4(bq, WH, kt, ntp, lane);
            #pragma unroll
            for (int mt = 0; mt < 4; mt++) {
                mmabf(acc[mt][2*ntp],   aH[mt], bq[0], bq[1]);
                mmabf(acc[mt][2*ntp+1], aH[mt], bq[2], bq[3]);
            }
        }
    }
    __syncwarp();
    epilogue_reg(acc, XH, lane, g_z2b + (size_t)bt*4096, g_psum2, g_psq2, bt);
}

// ---------------- K4: S = sum_t [relu(BN1(z1)) + relu(BN2(z2))]; edges ---------
__global__ void __launch_bounds__(256) k_sumfinal() {
    int bv = blockIdx.x, b = bv >> 6, v = bv & 63;
    int tid = threadIdx.x;
    int hq = (tid & 15) << 2, ph = tid >> 4;
    float4 A1 = *(float4*)&g_a1[hq], C1 = *(float4*)&g_c1[hq];
    float4 A2 = *(float4*)&g_a2[hq], C2 = *(float4*)&g_c2[hq];
    float4 s = make_float4(0.f,0.f,0.f,0.f);
    float4 e0 = s, e1 = s;
    #pragma unroll 4
    for (int t = ph; t < TT; t += 16) {
        size_t i1 = (((size_t)(b*TT + t))*64 + v)*64 + hq;
        uint2 u1 = *(const uint2*)&g_z1b[i1];
        uint2 u2 = *(const uint2*)&g_z2b[i1];
        float x0 = fmaxf(fmaf(__uint_as_float(u1.x << 16),         A1.x, C1.x), 0.f)
                 + fmaxf(fmaf(__uint_as_float(u2.x << 16),         A2.x, C2.x), 0.f);
        float x1 = fmaxf(fmaf(__uint_as_float(u1.x & 0xffff0000u), A1.y, C1.y), 0.f)
                 + fmaxf(fmaf(__uint_as_float(u2.x & 0xffff0000u), A2.y, C2.y), 0.f);
        float x2 = fmaxf(fmaf(__uint_as_float(u1.y << 16),         A1.z, C1.z), 0.f)
                 + fmaxf(fmaf(__uint_as_float(u2.y << 16),         A2.z, C2.z), 0.f);
        float x3 = fmaxf(fmaf(__uint_as_float(u1.y & 0xffff0000u), A1.w, C1.w), 0.f)
                 + fmaxf(fmaf(__uint_as_float(u2.y & 0xffff0000u), A2.w, C2.w), 0.f);
        s.x += x0; s.y += x1; s.z += x2; s.w += x3;
        if (t == 0)    e0 = make_float4(x0, x1, x2, x3);
        if (t == TT-1) e1 = make_float4(x0, x1, x2, x3);
    }
    __shared__ float sr[16][64], se0[64], se1[64];
    *(float4*)&sr[ph][hq] = s;
    if (ph == 0)  *(float4*)&se0[hq] = e0;
    if (ph == 15) *(float4*)&se1[hq] = e1;
    __syncthreads();
    if (tid < 64) {
        float S = 0.f;
        #pragma unroll
        for (int p = 0; p < 16; p++) S += sr[p][tid];
        int o = b*4096 + v*64 + tid;
        g_S[o]  = S;
        g_E0[o] = se0[tid];
        g_E1[o] = se1[tid];
    }
}

// ---------------- K5a: pool partials (i-tiles x o-tiles) ----------------------
__global__ void __launch_bounds__(256) k_poolA(const float* __restrict__ tw) {
    int itile = blockIdx.x;   // 0..31
    int otile = blockIdx.y;   // 0..15
    int tid = threadIdx.x, lane = tid & 31, wq = tid >> 5;
    __shared__ float sS[16][128], sE0[16][128], sE1[16][128];
    int i0 = itile*128;
    #pragma unroll
    for (int k = 0; k < 2; k++) {
        int i4 = k*256 + tid;
        int b = i4 >> 5, ii = (i4 & 31) << 2;
        *(float4*)&sS[b][ii]  = *(const float4*)&g_S [b*4096 + i0 + ii];
        *(float4*)&sE0[b][ii] = *(const float4*)&g_E0[b*4096 + i0 + ii];
        *(float4*)&sE1[b][ii] = *(const float4*)&g_E1[b*4096 + i0 + ii];
    }
    __syncthreads();
    #pragma unroll
    for (int pass = 0; pass < 2; pass++) {
        int o = otile*16 + pass*8 + wq;
        float acc[16];
        #pragma unroll
        for (int b = 0; b < 16; b++) acc[b] = 0.f;
        #pragma unroll
        for (int k = 0; k < 4; k++) {
            int i = k*32 + lane;
            const float* twp = tw + ((size_t)o*4096 + i0 + i)*3;
            float t0 = twp[0], t1 = twp[1], t2 = twp[2];
            float ts = t0 + t1 + t2;
            #pragma unroll
            for (int b = 0; b < 16; b++)
                acc[b] += ts*sS[b][i] - t0*sE1[b][i] - t2*sE0[b][i];
        }
        float mine = 0.f;
        #pragma unroll
        for (int b = 0; b < 16; b++) {
            float v = acc[b];
            #pragma unroll
            for (int d = 16; d > 0; d >>= 1) v += __shfl_xor_sync(0xffffffffu, v, d);
            if (lane == b) mine = v;
        }
        if (lane < 16) g_yp[((size_t)itile*256 + o)*16 + lane] = mine;
    }
}

// ---------------- K5b: reduce pool partials ------------------------------------
__global__ void __launch_bounds__(256) k_poolB(const float* __restrict__ tb) {
    int tid = threadIdx.x;
    int o = blockIdx.x*16 + (tid >> 4);
    int b = tid & 15;
    float s = 0.f;
    #pragma unroll 8
    for (int it = 0; it < 32; it++) s += g_yp[((size_t)it*256 + o)*16 + b];
    g_y[b*TC + o] = s*(1.f/TT) + tb[o];
}

// ---------------- K6: FC head ---------------------------------------------------
__global__ void __launch_bounds__(256) k_fc(const float* __restrict__ f1w,
                                            const float* __restrict__ f1b,
                                            const float* __restrict__ f2w,
                                            const float* __restrict__ f2b,
                                            float* __restrict__ out) {
    __shared__ float ys[BB*TC];
    __shared__ float hs[BB*128];
    int tid = threadIdx.x;
    for (int i = tid; i < BB*TC; i += 256) ys[i] = g_y[i];
    __syncthreads();
    int b = tid >> 4, jq = (tid & 15) * 8;
    float acc[8];
    #pragma unroll
    for (int j = 0; j < 8; j++) acc[j] = f1b[jq+j];
    for (int o = 0; o < TC; o++) {
        float yv = ys[b*TC + o];
        const float* w = f1w + o*128 + jq;
        #pragma unroll
        for (int j = 0; j < 8; j++) acc[j] += yv * w[j];
    }
    #pragma unroll
    for (int j = 0; j < 8; j++) hs[b*128 + jq + j] = fmaxf(acc[j], 0.f);
    __syncthreads();
    if (tid < BB*10) {
        int bb = tid / 10, n = tid % 10;
        float s = f2b[n];
        #pragma unroll 8
        for (int j = 0; j < 128; j++) s += hs[bb*128 + j] * f2w[j*10 + n];
        out[tid] = s;
    }
}

// ---------------- launch ---------------------------------------------------------
extern "C" void kernel_launch(void* const* d_in, const int* in_sizes, int n_in,
                              void* d_out, int out_size) {
    const float* x    = (const float*)d_in[0];
    const float* adj  = (const float*)d_in[1];
    const float* w1   = (const float*)d_in[2];
    const float* g1   = (const float*)d_in[4];
    const float* be1  = (const float*)d_in[5];
    const float* w2   = (const float*)d_in[6];
    const float* g2   = (const float*)d_in[8];
    const float* be2  = (const float*)d_in[9];
    const float* tw   = (const float*)d_in[10];
    const float* tb   = (const float*)d_in[11];
    const float* f1w  = (const float*)d_in[12];
    const float* f1b  = (const float*)d_in[13];
    const float* f2w  = (const float*)d_in[14];
    const float* f2b  = (const float*)d_in[15];
    float* out = (float*)d_out;

    cudaFuncSetAttribute(k_l1, cudaFuncAttributeMaxDynamicSharedMemorySize, L1_SM);
    cudaFuncSetAttribute(k_l2, cudaFuncAttributeMaxDynamicSharedMemorySize, L2_SM);

    k_prep<<<BB, 256>>>(adj, w1, w2);
    k_l1<<<BB*128, 128, L1_SM>>>(x);
    k_stats<<<HH, 256>>>(0, g1, be1);
    k_l2<<<BB*128, 128, L2_SM>>>();
    k_stats<<<HH, 256>>>(1, g2, be2);
    k_sumfinal<<<BB*VV, 256>>>();
    dim3 gp(32, 16);
    k_poolA<<<gp, 256>>>(tw);
    k_poolB<<<16, 256>>>(tb);
    k_fc<<<1, 256>>>(f1w, f1b, f2w, f2b, out);
}